// round 2
// baseline (speedup 1.0000x reference)
#include <cuda_runtime.h>
#include <math.h>

// ---------------- problem constants ----------------
#define B_    2048
#define DR_   1024
#define DI_   1024
#define DO_   1024
#define E_    8
#define TOPK_ 2
#define H1_   2048
#define H2_   2048
#define NS_   (B_ * TOPK_)          // 4096 token-slots
#define TILE_ 128
#define MAXROWS_ (NS_ + E_ * TILE_) // 5120 (padding per expert segment)
#define MAXTILES_ (MAXROWS_ / TILE_) // 40

// ---------------- device scratch (no allocations allowed) ----------------
__device__ float g_h1[MAXROWS_ * (size_t)H1_];   // 40 MB
__device__ float g_h2[MAXROWS_ * (size_t)H2_];   // 40 MB
__device__ float g_or[MAXROWS_ * (size_t)DO_];   // 20 MB
__device__ int   g_perm[MAXROWS_];
__device__ int   g_inv[NS_];
__device__ float g_gw[NS_];
__device__ int   g_idx[NS_];
__device__ int   g_count[E_];
__device__ int   g_cursor[E_];
__device__ int   g_base[E_];
__device__ int   g_tile_e[MAXTILES_];

// ---------------- f32x2 packed math helpers ----------------
__device__ __forceinline__ unsigned long long packf2(float lo, float hi) {
    unsigned long long r;
    asm("mov.b64 %0, {%1, %2};" : "=l"(r) : "f"(lo), "f"(hi));
    return r;
}
__device__ __forceinline__ void unpackf2(unsigned long long v, float& lo, float& hi) {
    asm("mov.b64 {%0, %1}, %2;" : "=f"(lo), "=f"(hi) : "l"(v));
}

// ---------------- init: reset all per-call state (graph replays!) ----------------
__global__ void init_k() {
    int i = blockIdx.x * blockDim.x + threadIdx.x;
    if (i < E_) { g_count[i] = 0; g_cursor[i] = 0; }
    if (i < MAXTILES_) g_tile_e[i] = -1;
    if (i < MAXROWS_) g_perm[i] = -1;
}

// ---------------- router: gate = x@Wg + bg, top-2, softmax ----------------
__global__ void router_k(const float* __restrict__ xr, const float* __restrict__ Wg,
                         const float* __restrict__ bg, const float* __restrict__ eb) {
    int t = blockIdx.x;
    int tid = threadIdx.x;
    const float* x = xr + (size_t)t * DR_;

    float acc[E_];
#pragma unroll
    for (int e = 0; e < E_; e++) acc[e] = 0.f;

    for (int d = tid; d < DR_; d += 256) {
        float xv = x[d];
        const float* w = Wg + (size_t)d * E_;
#pragma unroll
        for (int e = 0; e < E_; e++) acc[e] += xv * w[e];
    }

    __shared__ float red[E_][256];
#pragma unroll
    for (int e = 0; e < E_; e++) red[e][tid] = acc[e];
    __syncthreads();
    for (int s = 128; s > 0; s >>= 1) {
        if (tid < s) {
#pragma unroll
            for (int e = 0; e < E_; e++) red[e][tid] += red[e][tid + s];
        }
        __syncthreads();
    }

    if (tid == 0) {
        float gate[E_], sc[E_];
#pragma unroll
        for (int e = 0; e < E_; e++) {
            gate[e] = red[e][0] + bg[e];
            sc[e] = gate[e] + eb[e];
        }
        // top-2 with jax.lax.top_k tie semantics (earliest index wins on ties)
        int i0 = 0;
        for (int e = 1; e < E_; e++) if (sc[e] > sc[i0]) i0 = e;
        int i1 = -1;
        for (int e = 0; e < E_; e++) {
            if (e == i0) continue;
            if (i1 < 0 || sc[e] > sc[i1]) i1 = e;
        }
        float r0 = gate[i0], r1 = gate[i1];
        float m = fmaxf(r0, r1);
        float e0 = expf(r0 - m), e1 = expf(r1 - m);
        float inv = 1.f / (e0 + e1);
        g_idx[t * 2] = i0;  g_idx[t * 2 + 1] = i1;
        g_gw[t * 2] = e0 * inv;  g_gw[t * 2 + 1] = e1 * inv;
        atomicAdd(&g_count[i0], 1);
        atomicAdd(&g_count[i1], 1);
    }
}

// ---------------- prefix: padded per-expert segment bases + tile->expert map ----------------
__global__ void prefix_k() {
    if (blockIdx.x == 0 && threadIdx.x == 0) {
        int row = 0, nt = 0;
        for (int e = 0; e < E_; e++) {
            g_base[e] = row;
            int tiles = (g_count[e] + TILE_ - 1) / TILE_;
            for (int k = 0; k < tiles; k++) g_tile_e[nt++] = e;
            row += tiles * TILE_;
        }
    }
}

// ---------------- scatter: slot -> expert-sorted row ----------------
__global__ void scatter_k() {
    int s = blockIdx.x * blockDim.x + threadIdx.x;
    if (s >= NS_) return;
    int e = g_idx[s];
    int pos = atomicAdd(&g_cursor[e], 1);
    int r = g_base[e] + pos;
    g_perm[r] = s;
    g_inv[s] = r;
}

// ---------------- tiled GEMM: 128x128 block, BK=16, fma.rn.f32x2 core ----------------
// LAYER 1: gather x_expert rows via perm, K=1024, N=2048, ReLU -> g_h1
// LAYER 2: g_h1, K=2048, N=2048, ReLU -> g_h2
// LAYER 3: g_h2, K=2048, N=1024, +bias only -> g_or
template <int LAYER, int Kd, int Nd>
__global__ void __launch_bounds__(256, 2)
gemm_k(const float* __restrict__ Xin, const float* __restrict__ Wall,
       const float* __restrict__ Ball) {
    constexpr bool GATHER = (LAYER == 1);
    constexpr bool RELU = (LAYER < 3);

    int rt = blockIdx.y, ct = blockIdx.x;
    int e = g_tile_e[rt];
    if (e < 0) return;

    const float* W    = Wall + (size_t)e * Kd * Nd;
    const float* bias = Ball + (size_t)e * Nd;
    int row0 = rt * TILE_, col0 = ct * TILE_;

    const float* Ain;
    float* Cout;
    if (LAYER == 1)      { Ain = nullptr; Cout = g_h1; }
    else if (LAYER == 2) { Ain = g_h1;    Cout = g_h2; }
    else                 { Ain = g_h2;    Cout = g_or; }

    __shared__ __align__(16) float As[2][16][128];
    __shared__ __align__(16) float Bs[2][16][128];

    int tid = threadIdx.x;
    int tx = tid & 15, ty = tid >> 4;

    // A-tile load mapping: thread -> (row am, k-chunk ak of 8 floats)
    int am = tid >> 1;
    int ak = (tid & 1) * 8;
    const float* Arow;
    if (GATHER) {
        int slot = g_perm[row0 + am];
        Arow = (slot >= 0) ? (Xin + (size_t)(slot >> 1) * Kd) : nullptr;
    } else {
        Arow = Ain + (size_t)(row0 + am) * Kd;
    }

    // B-tile load mapping: thread -> rows (bk, bk+8), 4 cols at bc
    int bk = tid >> 5;
    int bc = (tid & 31) * 4;
    const float* Bbase = W + (size_t)bk * Nd + col0 + bc;

    unsigned long long acc[4][8];
#pragma unroll
    for (int ip = 0; ip < 4; ip++)
#pragma unroll
        for (int j = 0; j < 8; j++) acc[ip][j] = 0ULL;

    constexpr int KT = Kd / 16;

    // prologue: tile 0 -> buf 0
    {
        float4 a0, a1, b0, b1;
        if (!GATHER || Arow) {
            a0 = *(const float4*)(Arow + ak);
            a1 = *(const float4*)(Arow + ak + 4);
        } else {
            a0 = make_float4(0.f, 0.f, 0.f, 0.f); a1 = a0;
        }
        b0 = *(const float4*)(Bbase);
        b1 = *(const float4*)(Bbase + (size_t)8 * Nd);
        As[0][ak + 0][am] = a0.x; As[0][ak + 1][am] = a0.y;
        As[0][ak + 2][am] = a0.z; As[0][ak + 3][am] = a0.w;
        As[0][ak + 4][am] = a1.x; As[0][ak + 5][am] = a1.y;
        As[0][ak + 6][am] = a1.z; As[0][ak + 7][am] = a1.w;
        *(float4*)&Bs[0][bk][bc]     = b0;
        *(float4*)&Bs[0][bk + 8][bc] = b1;
    }
    __syncthreads();

    int buf = 0;
    for (int kt = 0; kt < KT; kt++) {
        float4 na0, na1, nb0, nb1;
        bool more = (kt + 1 < KT);
        if (more) {
            int k0 = (kt + 1) * 16;
            if (!GATHER || Arow) {
                na0 = *(const float4*)(Arow + k0 + ak);
                na1 = *(const float4*)(Arow + k0 + ak + 4);
            } else {
                na0 = make_float4(0.f, 0.f, 0.f, 0.f); na1 = na0;
            }
            nb0 = *(const float4*)(Bbase + (size_t)k0 * Nd);
            nb1 = *(const float4*)(Bbase + (size_t)(k0 + 8) * Nd);
        }

#pragma unroll
        for (int kk = 0; kk < 16; kk++) {
            unsigned long long a2[4];
#pragma unroll
            for (int ip = 0; ip < 4; ip++)
                a2[ip] = *(const unsigned long long*)&As[buf][kk][ty * 8 + 2 * ip];
            float4 bq0 = *(const float4*)&Bs[buf][kk][tx * 8];
            float4 bq1 = *(const float4*)&Bs[buf][kk][tx * 8 + 4];
            unsigned long long b2[8];
            b2[0] = packf2(bq0.x, bq0.x); b2[1] = packf2(bq0.y, bq0.y);
            b2[2] = packf2(bq0.z, bq0.z); b2[3] = packf2(bq0.w, bq0.w);
            b2[4] = packf2(bq1.x, bq1.x); b2[5] = packf2(bq1.y, bq1.y);
            b2[6] = packf2(bq1.z, bq1.z); b2[7] = packf2(bq1.w, bq1.w);
#pragma unroll
            for (int ip = 0; ip < 4; ip++)
#pragma unroll
                for (int j = 0; j < 8; j++)
                    asm("fma.rn.f32x2 %0, %1, %2, %0;"
                        : "+l"(acc[ip][j]) : "l"(a2[ip]), "l"(b2[j]));
        }

        if (more) {
            int nb = buf ^ 1;
            As[nb][ak + 0][am] = na0.x; As[nb][ak + 1][am] = na0.y;
            As[nb][ak + 2][am] = na0.z; As[nb][ak + 3][am] = na0.w;
            As[nb][ak + 4][am] = na1.x; As[nb][ak + 5][am] = na1.y;
            As[nb][ak + 6][am] = na1.z; As[nb][ak + 7][am] = na1.w;
            *(float4*)&Bs[nb][bk][bc]     = nb0;
            *(float4*)&Bs[nb][bk + 8][bc] = nb1;
            __syncthreads();
            buf = nb;
        }
    }

    // epilogue: +bias, optional ReLU, store two rows per ip
    float4 bv0 = *(const float4*)(bias + col0 + tx * 8);
    float4 bv1 = *(const float4*)(bias + col0 + tx * 8 + 4);
#pragma unroll
    for (int ip = 0; ip < 4; ip++) {
        float lo[8], hi[8];
#pragma unroll
        for (int j = 0; j < 8; j++) unpackf2(acc[ip][j], lo[j], hi[j]);
        int r = row0 + ty * 8 + 2 * ip;
        float* c0 = Cout + (size_t)r * Nd + col0 + tx * 8;
        float* c1 = c0 + Nd;

        float4 o;
        o.x = lo[0] + bv0.x; o.y = lo[1] + bv0.y; o.z = lo[2] + bv0.z; o.w = lo[3] + bv0.w;
        if (RELU) { o.x = fmaxf(o.x, 0.f); o.y = fmaxf(o.y, 0.f); o.z = fmaxf(o.z, 0.f); o.w = fmaxf(o.w, 0.f); }
        *(float4*)c0 = o;
        o.x = lo[4] + bv1.x; o.y = lo[5] + bv1.y; o.z = lo[6] + bv1.z; o.w = lo[7] + bv1.w;
        if (RELU) { o.x = fmaxf(o.x, 0.f); o.y = fmaxf(o.y, 0.f); o.z = fmaxf(o.z, 0.f); o.w = fmaxf(o.w, 0.f); }
        *(float4*)(c0 + 4) = o;

        o.x = hi[0] + bv0.x; o.y = hi[1] + bv0.y; o.z = hi[2] + bv0.z; o.w = hi[3] + bv0.w;
        if (RELU) { o.x = fmaxf(o.x, 0.f); o.y = fmaxf(o.y, 0.f); o.z = fmaxf(o.z, 0.f); o.w = fmaxf(o.w, 0.f); }
        *(float4*)c1 = o;
        o.x = hi[4] + bv1.x; o.y = hi[5] + bv1.y; o.z = hi[6] + bv1.z; o.w = hi[7] + bv1.w;
        if (RELU) { o.x = fmaxf(o.x, 0.f); o.y = fmaxf(o.y, 0.f); o.z = fmaxf(o.z, 0.f); o.w = fmaxf(o.w, 0.f); }
        *(float4*)(c1 + 4) = o;
    }
}

// ---------------- combine: final[t] = gw0*or[inv[2t]] + gw1*or[inv[2t+1]] ----------------
__global__ void combine_k(float* __restrict__ out) {
    int t = blockIdx.x;
    int c = threadIdx.x;  // 256 threads, one float4 each (DO_=1024)
    int r0 = g_inv[t * 2], r1 = g_inv[t * 2 + 1];
    float w0 = g_gw[t * 2], w1 = g_gw[t * 2 + 1];
    const float4* a = (const float4*)(g_or + (size_t)r0 * DO_);
    const float4* b = (const float4*)(g_or + (size_t)r1 * DO_);
    float4 va = a[c], vb = b[c], o;
    o.x = w0 * va.x + w1 * vb.x;
    o.y = w0 * va.y + w1 * vb.y;
    o.z = w0 * va.z + w1 * vb.z;
    o.w = w0 * va.w + w1 * vb.w;
    ((float4*)(out + (size_t)t * DO_))[c] = o;
}

// ---------------- optional idx output (if harness concatenates (final, idx)) ----------------
__global__ void idxout_k(float* __restrict__ dst, int n) {
    int i = blockIdx.x * blockDim.x + threadIdx.x;
    if (i < n) dst[i] = (float)g_idx[i];
}

// ---------------- launch ----------------
extern "C" void kernel_launch(void* const* d_in, const int* in_sizes, int n_in,
                              void* d_out, int out_size) {
    (void)in_sizes; (void)n_in;
    const float* xr = (const float*)d_in[0];   // x_router_input [B, DR]
    const float* xe = (const float*)d_in[1];   // x_expert_input [B, DI]
    const float* Wg = (const float*)d_in[2];   // [DR, E]
    const float* bg = (const float*)d_in[3];   // [E]
    const float* eb = (const float*)d_in[4];   // expert_biases [E]
    const float* W1 = (const float*)d_in[5];   // [E, DI, H1]
    const float* b1 = (const float*)d_in[6];   // [E, H1]
    const float* W2 = (const float*)d_in[7];   // [E, H1, H2]
    const float* b2 = (const float*)d_in[8];   // [E, H2]
    const float* W3 = (const float*)d_in[9];   // [E, H2, DO]
    const float* b3 = (const float*)d_in[10];  // [E, DO]
    float* out = (float*)d_out;

    init_k<<<(MAXROWS_ + 255) / 256, 256>>>();
    router_k<<<B_, 256>>>(xr, Wg, bg, eb);
    prefix_k<<<1, 1>>>();
    scatter_k<<<NS_ / 256, 256>>>();

    gemm_k<1, DI_, H1_><<<dim3(H1_ / TILE_, MAXTILES_), 256>>>(xe, W1, b1);
    gemm_k<2, H1_, H2_><<<dim3(H2_ / TILE_, MAXTILES_), 256>>>(nullptr, W2, b2);
    gemm_k<3, H2_, DO_><<<dim3(DO_ / TILE_, MAXTILES_), 256>>>(nullptr, W3, b3);

    combine_k<<<B_, 256>>>(out);

    // If the harness output buffer also carries the idx tensor (flattened,
    // cast to the output dtype), fill the tail.
    int tail = out_size - B_ * DO_;
    if (tail > 0) {
        int n = tail < NS_ ? tail : NS_;
        idxout_k<<<(n + 255) / 256, 256>>>(out + (size_t)B_ * DO_, n);
    }
}

// round 4
// speedup vs baseline: 1.4575x; 1.4575x over previous
#include <cuda_runtime.h>
#include <cuda_bf16.h>
#include <math.h>
#include <stdint.h>

// ---------------- problem constants ----------------
#define B_    2048
#define DR_   1024
#define DI_   1024
#define DO_   1024
#define E_    8
#define TOPK_ 2
#define H1_   2048
#define H2_   2048
#define NS_   (B_ * TOPK_)
#define TILE_ 128
#define MAXROWS_ (NS_ + E_ * TILE_)   // 5120
#define MAXTILES_ (MAXROWS_ / TILE_)  // 40

// ---------------- device scratch ----------------
__device__ float g_h1[MAXROWS_ * (size_t)H1_];
__device__ float g_h2[MAXROWS_ * (size_t)H2_];
__device__ float g_or[MAXROWS_ * (size_t)DO_];
__device__ int   g_perm[MAXROWS_];
__device__ int   g_inv[NS_];
__device__ float g_gw[NS_];
__device__ int   g_idx[NS_];
__device__ int   g_count[E_];
__device__ int   g_cursor[E_];
__device__ int   g_base[E_];
__device__ int   g_tile_e[MAXTILES_];

// bf16 split + transposed weights: [e][N][K] (K-major rows)
__device__ __nv_bfloat16 g_w1h[(size_t)E_ * H1_ * DI_];
__device__ __nv_bfloat16 g_w1l[(size_t)E_ * H1_ * DI_];
__device__ __nv_bfloat16 g_w2h[(size_t)E_ * H2_ * H1_];
__device__ __nv_bfloat16 g_w2l[(size_t)E_ * H2_ * H1_];
__device__ __nv_bfloat16 g_w3h[(size_t)E_ * DO_ * H2_];
__device__ __nv_bfloat16 g_w3l[(size_t)E_ * DO_ * H2_];

// ---------------- cp.async helpers (sm_80 baseline, safe on compute_103) ----
__device__ __forceinline__ uint32_t smem_u32(const void* p) {
    uint32_t a;
    asm("{ .reg .u64 t; cvta.to.shared.u64 t, %1; cvt.u32.u64 %0, t; }" : "=r"(a) : "l"(p));
    return a;
}
#define CP_ASYNC16(dst_u32, src_gptr) \
    asm volatile("cp.async.cg.shared.global [%0], [%1], 16;" :: "r"(dst_u32), "l"(src_gptr))
#define CP_COMMIT() asm volatile("cp.async.commit_group;" ::: "memory")
#define CP_WAIT1()  asm volatile("cp.async.wait_group 1;" ::: "memory")
#define CP_WAIT0()  asm volatile("cp.async.wait_group 0;" ::: "memory")

// ---------------- mma.sync bf16 (HMMA) ----------------
__device__ __forceinline__ void mma16816(float* d, const uint32_t* a, const uint32_t* b) {
    asm volatile(
        "mma.sync.aligned.m16n8k16.row.col.f32.bf16.bf16.f32 "
        "{%0,%1,%2,%3}, {%4,%5,%6,%7}, {%8,%9}, {%0,%1,%2,%3};"
        : "+f"(d[0]), "+f"(d[1]), "+f"(d[2]), "+f"(d[3])
        : "r"(a[0]), "r"(a[1]), "r"(a[2]), "r"(a[3]), "r"(b[0]), "r"(b[1]));
}

// ---------------- init / router / prefix / scatter ----------------
__global__ void init_k() {
    int i = blockIdx.x * blockDim.x + threadIdx.x;
    if (i < E_) { g_count[i] = 0; g_cursor[i] = 0; }
    if (i < MAXTILES_) g_tile_e[i] = -1;
    if (i < MAXROWS_) g_perm[i] = -1;
}

__global__ void router_k(const float* __restrict__ xr, const float* __restrict__ Wg,
                         const float* __restrict__ bg, const float* __restrict__ eb) {
    int t = blockIdx.x, tid = threadIdx.x;
    const float* x = xr + (size_t)t * DR_;
    float acc[E_];
#pragma unroll
    for (int e = 0; e < E_; e++) acc[e] = 0.f;
    for (int d = tid; d < DR_; d += 256) {
        float xv = x[d];
        const float* w = Wg + (size_t)d * E_;
#pragma unroll
        for (int e = 0; e < E_; e++) acc[e] += xv * w[e];
    }
    __shared__ float red[E_][256];
#pragma unroll
    for (int e = 0; e < E_; e++) red[e][tid] = acc[e];
    __syncthreads();
    for (int s = 128; s > 0; s >>= 1) {
        if (tid < s)
#pragma unroll
            for (int e = 0; e < E_; e++) red[e][tid] += red[e][tid + s];
        __syncthreads();
    }
    if (tid == 0) {
        float gate[E_], sc[E_];
#pragma unroll
        for (int e = 0; e < E_; e++) { gate[e] = red[e][0] + bg[e]; sc[e] = gate[e] + eb[e]; }
        int i0 = 0;
        for (int e = 1; e < E_; e++) if (sc[e] > sc[i0]) i0 = e;
        int i1 = -1;
        for (int e = 0; e < E_; e++) {
            if (e == i0) continue;
            if (i1 < 0 || sc[e] > sc[i1]) i1 = e;
        }
        float r0 = gate[i0], r1 = gate[i1];
        float m = fmaxf(r0, r1);
        float e0 = expf(r0 - m), e1 = expf(r1 - m);
        float inv = 1.f / (e0 + e1);
        g_idx[t * 2] = i0; g_idx[t * 2 + 1] = i1;
        g_gw[t * 2] = e0 * inv; g_gw[t * 2 + 1] = e1 * inv;
        atomicAdd(&g_count[i0], 1);
        atomicAdd(&g_count[i1], 1);
    }
}

__global__ void prefix_k() {
    if (blockIdx.x == 0 && threadIdx.x == 0) {
        int row = 0, nt = 0;
        for (int e = 0; e < E_; e++) {
            g_base[e] = row;
            int tiles = (g_count[e] + TILE_ - 1) / TILE_;
            for (int k = 0; k < tiles; k++) g_tile_e[nt++] = e;
            row += tiles * TILE_;
        }
    }
}

__global__ void scatter_k() {
    int s = blockIdx.x * blockDim.x + threadIdx.x;
    if (s >= NS_) return;
    int e = g_idx[s];
    int pos = atomicAdd(&g_cursor[e], 1);
    int r = g_base[e] + pos;
    g_perm[r] = s;
    g_inv[s] = r;
}

// ---------------- weight transpose + bf16 hi/lo split: [e][K][N] -> [e][N][K] ----
template <int LAYER>
__global__ void wsplit_k(const float* __restrict__ W, int K, int N) {
    __nv_bfloat16 *Wh, *Wl;
    if (LAYER == 1)      { Wh = g_w1h; Wl = g_w1l; }
    else if (LAYER == 2) { Wh = g_w2h; Wl = g_w2l; }
    else                 { Wh = g_w3h; Wl = g_w3l; }
    __shared__ float t[32][33];
    int e = blockIdx.z;
    const float* We = W + (size_t)e * K * N;
    size_t ob = (size_t)e * K * N;
    int n0 = blockIdx.x * 32, k0 = blockIdx.y * 32;
    int tx = threadIdx.x, ty = threadIdx.y;
#pragma unroll
    for (int r = 0; r < 4; r++)
        t[ty + 8 * r][tx] = We[(size_t)(k0 + ty + 8 * r) * N + n0 + tx];
    __syncthreads();
#pragma unroll
    for (int r = 0; r < 4; r++) {
        int n = ty + 8 * r;
        float v = t[tx][n];
        __nv_bfloat16 h = __float2bfloat16(v);
        __nv_bfloat16 l = __float2bfloat16(v - __bfloat162float(h));
        size_t o = ob + (size_t)(n0 + n) * K + k0 + tx;
        Wh[o] = h; Wl[o] = l;
    }
}

// ---------------- fp32 -> bf16 hi/lo split of 8 values ----------------
static __device__ __forceinline__ void split8(float4 v0, float4 v1, uint4& h, uint4& l) {
    float a[8] = {v0.x, v0.y, v0.z, v0.w, v1.x, v1.y, v1.z, v1.w};
    uint32_t hh[4], ll[4];
#pragma unroll
    for (int i = 0; i < 4; i++) {
        __nv_bfloat162 hb = __floats2bfloat162_rn(a[2 * i], a[2 * i + 1]);
        float ra = a[2 * i]     - __bfloat162float(hb.x);
        float rb = a[2 * i + 1] - __bfloat162float(hb.y);
        __nv_bfloat162 lb = __floats2bfloat162_rn(ra, rb);
        hh[i] = *reinterpret_cast<uint32_t*>(&hb);
        ll[i] = *reinterpret_cast<uint32_t*>(&lb);
    }
    h = make_uint4(hh[0], hh[1], hh[2], hh[3]);
    l = make_uint4(ll[0], ll[1], ll[2], ll[3]);
}

// ---------------- HMMA GEMM: 128x128 CTA tile, BK=32, bf16x3 split ----------------
// smem stage layout (padded rows: 32 bf16 data = 64B, stride 80B -> conflict-free):
//   Ah @ 0      (128 rows * 80B = 10240)
//   Al @ 10240
//   Bh @ 20480  (128 n-rows * 80B)
//   Bl @ 30720
#define ROWB   80
#define REGION 10240
#define STAGE  40960
#define SMEM_GEMM (2 * STAGE)

template <int LAYER, int Kd, int Nd>
__global__ void __launch_bounds__(256, 1)
mma_gemm_k(const float* __restrict__ Xe, const float* __restrict__ Ball) {
    extern __shared__ __align__(128) char smem[];
    int rt = blockIdx.y, ct = blockIdx.x;
    int e = g_tile_e[rt];
    if (e < 0) return;

    const __nv_bfloat16 *Wh, *Wl;
    const float* Ain;
    float* Cout;
    if (LAYER == 1)      { Wh = g_w1h; Wl = g_w1l; Ain = Xe;   Cout = g_h1; }
    else if (LAYER == 2) { Wh = g_w2h; Wl = g_w2l; Ain = g_h1; Cout = g_h2; }
    else                 { Wh = g_w3h; Wl = g_w3l; Ain = g_h2; Cout = g_or; }

    int row0 = rt * 128, col0 = ct * 128;
    const float* bias = Ball + (size_t)e * Nd;

    int tid = threadIdx.x, wid = tid >> 5, lid = tid & 31;
    int g = lid >> 2, t = lid & 3;
    int wm = wid & 1, wn = wid >> 1;          // warp grid 2(M) x 4(N)
    int m_base = wm * 64, n_base = wn * 32;

    // ---- fill mapping: thread -> (row, half) ----
    int arow = tid >> 1, half = tid & 1;      // 128 rows x 2 halves of 16 elems
    const float* Arow;
    if (LAYER == 1) {
        int slot = g_perm[row0 + arow];
        Arow = (slot >= 0) ? (Ain + (size_t)(slot >> 1) * Kd) : nullptr;
    } else {
        Arow = Ain + (size_t)(row0 + arow) * Kd;
    }
    const __nv_bfloat16* BhRow = Wh + (size_t)e * Nd * Kd + (size_t)(col0 + arow) * Kd;
    const __nv_bfloat16* BlRow = Wl + (size_t)e * Nd * Kd + (size_t)(col0 + arow) * Kd;

    uint32_t sbase = smem_u32(smem);
    uint32_t fill_off = (uint32_t)arow * ROWB + half * 32;

    float acc[4][4][4];
#pragma unroll
    for (int mt = 0; mt < 4; mt++)
#pragma unroll
        for (int nt = 0; nt < 4; nt++)
#pragma unroll
            for (int q = 0; q < 4; q++) acc[mt][nt][q] = 0.f;

    constexpr int KC = Kd / 32;

    // ---- fill stage: A via ld+split+STS, B via cp.async ----
    auto fill = [&](int kc) {
        int s = kc & 1;
        char* st = smem + s * STAGE;
        int k0 = kc * 32;
        // A fp32 -> hi/lo bf16
        if (LAYER != 1 || Arow) {
            const float4* src = (const float4*)(Arow + k0 + half * 16);
            float4 v0 = src[0], v1 = src[1], v2 = src[2], v3 = src[3];
            uint4 h0, l0, h1, l1;
            split8(v0, v1, h0, l0);
            split8(v2, v3, h1, l1);
            *(uint4*)(st + fill_off)                 = h0;
            *(uint4*)(st + fill_off + 16)            = h1;
            *(uint4*)(st + REGION + fill_off)        = l0;
            *(uint4*)(st + REGION + fill_off + 16)   = l1;
        } else {
            uint4 z = make_uint4(0, 0, 0, 0);
            *(uint4*)(st + fill_off)               = z;
            *(uint4*)(st + fill_off + 16)          = z;
            *(uint4*)(st + REGION + fill_off)      = z;
            *(uint4*)(st + REGION + fill_off + 16) = z;
        }
        // B bf16 straight copy via cp.async (16B x2 per hi/lo)
        uint32_t dstb = sbase + s * STAGE + fill_off;
        CP_ASYNC16(dstb + 2 * REGION,      BhRow + k0 + half * 16);
        CP_ASYNC16(dstb + 2 * REGION + 16, BhRow + k0 + half * 16 + 8);
        CP_ASYNC16(dstb + 3 * REGION,      BlRow + k0 + half * 16);
        CP_ASYNC16(dstb + 3 * REGION + 16, BlRow + k0 + half * 16 + 8);
        CP_COMMIT();
    };

    fill(0);

    for (int kc = 0; kc < KC; kc++) {
        if (kc + 1 < KC) { fill(kc + 1); CP_WAIT1(); }
        else             { CP_WAIT0(); }
        __syncthreads();

        const char* st = smem + (kc & 1) * STAGE;
#pragma unroll
        for (int ks = 0; ks < 2; ks++) {
            uint32_t ah[4][4], al[4][4], bh[4][2], bl[4][2];
#pragma unroll
            for (int mt = 0; mt < 4; mt++) {
                uint32_t ao = (uint32_t)(m_base + mt * 16 + g) * ROWB + ks * 32 + t * 4;
                ah[mt][0] = *(const uint32_t*)(st + ao);
                ah[mt][1] = *(const uint32_t*)(st + ao + 8 * ROWB);
                ah[mt][2] = *(const uint32_t*)(st + ao + 16);
                ah[mt][3] = *(const uint32_t*)(st + ao + 8 * ROWB + 16);
                al[mt][0] = *(const uint32_t*)(st + REGION + ao);
                al[mt][1] = *(const uint32_t*)(st + REGION + ao + 8 * ROWB);
                al[mt][2] = *(const uint32_t*)(st + REGION + ao + 16);
                al[mt][3] = *(const uint32_t*)(st + REGION + ao + 8 * ROWB + 16);
            }
#pragma unroll
            for (int nt = 0; nt < 4; nt++) {
                uint32_t bo = (uint32_t)(n_base + nt * 8 + g) * ROWB + ks * 32 + t * 4;
                bh[nt][0] = *(const uint32_t*)(st + 2 * REGION + bo);
                bh[nt][1] = *(const uint32_t*)(st + 2 * REGION + bo + 16);
                bl[nt][0] = *(const uint32_t*)(st + 3 * REGION + bo);
                bl[nt][1] = *(const uint32_t*)(st + 3 * REGION + bo + 16);
            }
#pragma unroll
            for (int mt = 0; mt < 4; mt++)
#pragma unroll
                for (int nt = 0; nt < 4; nt++) {
                    mma16816(acc[mt][nt], ah[mt], bh[nt]);
                    mma16816(acc[mt][nt], al[mt], bh[nt]);
                    mma16816(acc[mt][nt], ah[mt], bl[nt]);
                }
        }
        __syncthreads();
    }

    // ---- epilogue: +bias, ReLU, store ----
#pragma unroll
    for (int mt = 0; mt < 4; mt++) {
        int r0 = row0 + m_base + mt * 16 + g;
#pragma unroll
        for (int nt = 0; nt < 4; nt++) {
            int col = col0 + n_base + nt * 8 + t * 2;
            float2 bv = *(const float2*)(bias + col);
            float2 o0, o1;
            o0.x = acc[mt][nt][0] + bv.x; o0.y = acc[mt][nt][1] + bv.y;
            o1.x = acc[mt][nt][2] + bv.x; o1.y = acc[mt][nt][3] + bv.y;
            if (LAYER < 3) {
                o0.x = fmaxf(o0.x, 0.f); o0.y = fmaxf(o0.y, 0.f);
                o1.x = fmaxf(o1.x, 0.f); o1.y = fmaxf(o1.y, 0.f);
            }
            *(float2*)(Cout + (size_t)r0 * Nd + col)       = o0;
            *(float2*)(Cout + (size_t)(r0 + 8) * Nd + col) = o1;
        }
    }
}

// ---------------- combine ----------------
__global__ void combine_k(float* __restrict__ out) {
    int t = blockIdx.x, c = threadIdx.x;
    int r0 = g_inv[t * 2], r1 = g_inv[t * 2 + 1];
    float w0 = g_gw[t * 2], w1 = g_gw[t * 2 + 1];
    const float4* a = (const float4*)(g_or + (size_t)r0 * DO_);
    const float4* b = (const float4*)(g_or + (size_t)r1 * DO_);
    float4 va = a[c], vb = b[c], o;
    o.x = w0 * va.x + w1 * vb.x;
    o.y = w0 * va.y + w1 * vb.y;
    o.z = w0 * va.z + w1 * vb.z;
    o.w = w0 * va.w + w1 * vb.w;
    ((float4*)(out + (size_t)t * DO_))[c] = o;
}

__global__ void idxout_k(float* __restrict__ dst, int n) {
    int i = blockIdx.x * blockDim.x + threadIdx.x;
    if (i < n) dst[i] = (float)g_idx[i];
}

// ---------------- launch ----------------
extern "C" void kernel_launch(void* const* d_in, const int* in_sizes, int n_in,
                              void* d_out, int out_size) {
    (void)in_sizes; (void)n_in;
    const float* xr = (const float*)d_in[0];
    const float* xe = (const float*)d_in[1];
    const float* Wg = (const float*)d_in[2];
    const float* bg = (const float*)d_in[3];
    const float* eb = (const float*)d_in[4];
    const float* W1 = (const float*)d_in[5];
    const float* b1 = (const float*)d_in[6];
    const float* W2 = (const float*)d_in[7];
    const float* b2 = (const float*)d_in[8];
    const float* W3 = (const float*)d_in[9];
    const float* b3 = (const float*)d_in[10];
    float* out = (float*)d_out;

    cudaFuncSetAttribute(mma_gemm_k<1, DI_, H1_>, cudaFuncAttributeMaxDynamicSharedMemorySize, SMEM_GEMM);
    cudaFuncSetAttribute(mma_gemm_k<2, H1_, H2_>, cudaFuncAttributeMaxDynamicSharedMemorySize, SMEM_GEMM);
    cudaFuncSetAttribute(mma_gemm_k<3, H2_, DO_>, cudaFuncAttributeMaxDynamicSharedMemorySize, SMEM_GEMM);

    init_k<<<(MAXROWS_ + 255) / 256, 256>>>();
    router_k<<<B_, 256>>>(xr, Wg, bg, eb);

    dim3 wt(32, 8);
    wsplit_k<1><<<dim3(H1_ / 32, DI_ / 32, E_), wt>>>(W1, DI_, H1_);
    wsplit_k<2><<<dim3(H2_ / 32, H1_ / 32, E_), wt>>>(W2, H1_, H2_);
    wsplit_k<3><<<dim3(DO_ / 32, H2_ / 32, E_), wt>>>(W3, H2_, DO_);

    prefix_k<<<1, 1>>>();
    scatter_k<<<NS_ / 256, 256>>>();

    mma_gemm_k<1, DI_, H1_><<<dim3(H1_ / 128, MAXTILES_), 256, SMEM_GEMM>>>(xe, b1);
    mma_gemm_k<2, H1_, H2_><<<dim3(H2_ / 128, MAXTILES_), 256, SMEM_GEMM>>>(nullptr, b2);
    mma_gemm_k<3, H2_, DO_><<<dim3(DO_ / 128, MAXTILES_), 256, SMEM_GEMM>>>(nullptr, b3);

    combine_k<<<B_, 256>>>(out);

    int tail = out_size - B_ * DO_;
    if (tail > 0) {
        int n = tail < NS_ ? tail : NS_;
        idxout_k<<<(n + 255) / 256, 256>>>(out + (size_t)B_ * DO_, n);
    }
}

// round 5
// speedup vs baseline: 1.6123x; 1.1063x over previous
#include <cuda_runtime.h>
#include <cuda_bf16.h>
#include <math.h>
#include <stdint.h>

// ---------------- problem constants ----------------
#define B_    2048
#define DR_   1024
#define DI_   1024
#define DO_   1024
#define E_    8
#define TOPK_ 2
#define H1_   2048
#define H2_   2048
#define NS_   (B_ * TOPK_)
#define TILE_ 128
#define MAXROWS_ (NS_ + E_ * TILE_)   // 5120
#define MAXTILES_ (MAXROWS_ / TILE_)  // 40

// ---------------- device scratch ----------------
__device__ float g_or[MAXROWS_ * (size_t)DO_];
__device__ int   g_perm[MAXROWS_];
__device__ int   g_inv[NS_];
__device__ float g_gw[NS_];
__device__ int   g_idx[NS_];
__device__ int   g_count[E_];
__device__ int   g_cursor[E_];
__device__ int   g_base[E_];
__device__ int   g_tile_e[MAXTILES_];

// bf16 split + transposed weights: [e][N][K]
__device__ __nv_bfloat16 g_w1h[(size_t)E_ * H1_ * DI_];
__device__ __nv_bfloat16 g_w1l[(size_t)E_ * H1_ * DI_];
__device__ __nv_bfloat16 g_w2h[(size_t)E_ * H2_ * H1_];
__device__ __nv_bfloat16 g_w2l[(size_t)E_ * H2_ * H1_];
__device__ __nv_bfloat16 g_w3h[(size_t)E_ * DO_ * H2_];
__device__ __nv_bfloat16 g_w3l[(size_t)E_ * DO_ * H2_];

// bf16 split activations
__device__ __nv_bfloat16 g_xh[(size_t)B_ * DI_];
__device__ __nv_bfloat16 g_xl[(size_t)B_ * DI_];
__device__ __nv_bfloat16 g_a1h[MAXROWS_ * (size_t)H1_];
__device__ __nv_bfloat16 g_a1l[MAXROWS_ * (size_t)H1_];
__device__ __nv_bfloat16 g_a2h[MAXROWS_ * (size_t)H2_];
__device__ __nv_bfloat16 g_a2l[MAXROWS_ * (size_t)H2_];

// ---------------- PTX helpers ----------------
__device__ __forceinline__ uint32_t smem_u32(const void* p) {
    uint32_t a;
    asm("{ .reg .u64 t; cvta.to.shared.u64 t, %1; cvt.u32.u64 %0, t; }" : "=r"(a) : "l"(p));
    return a;
}
#define CP16(dst, src) \
    asm volatile("cp.async.cg.shared.global [%0], [%1], 16;" :: "r"(dst), "l"(src))
#define CP16Z(dst, src, n) \
    asm volatile("cp.async.cg.shared.global [%0], [%1], 16, %2;" :: "r"(dst), "l"(src), "r"(n))
#define CP_COMMIT() asm volatile("cp.async.commit_group;" ::: "memory")
#define CP_WAIT2()  asm volatile("cp.async.wait_group 2;" ::: "memory")

__device__ __forceinline__ void ldm_x4(uint32_t* r, uint32_t addr) {
    asm volatile("ldmatrix.sync.aligned.m8n8.x4.shared.b16 {%0,%1,%2,%3}, [%4];"
                 : "=r"(r[0]), "=r"(r[1]), "=r"(r[2]), "=r"(r[3]) : "r"(addr));
}
__device__ __forceinline__ void mma16816(float* d, const uint32_t* a, uint32_t b0, uint32_t b1) {
    asm volatile(
        "mma.sync.aligned.m16n8k16.row.col.f32.bf16.bf16.f32 "
        "{%0,%1,%2,%3}, {%4,%5,%6,%7}, {%8,%9}, {%0,%1,%2,%3};"
        : "+f"(d[0]), "+f"(d[1]), "+f"(d[2]), "+f"(d[3])
        : "r"(a[0]), "r"(a[1]), "r"(a[2]), "r"(a[3]), "r"(b0), "r"(b1));
}

// ---------------- init / router / prefix / scatter ----------------
__global__ void init_k() {
    int i = blockIdx.x * blockDim.x + threadIdx.x;
    if (i < E_) { g_count[i] = 0; g_cursor[i] = 0; }
    if (i < MAXTILES_) g_tile_e[i] = -1;
    if (i < MAXROWS_) g_perm[i] = -1;
}

__global__ void router_k(const float* __restrict__ xr, const float* __restrict__ Wg,
                         const float* __restrict__ bg, const float* __restrict__ eb) {
    int t = blockIdx.x, tid = threadIdx.x;
    const float* x = xr + (size_t)t * DR_;
    float acc[E_];
#pragma unroll
    for (int e = 0; e < E_; e++) acc[e] = 0.f;
    for (int d = tid; d < DR_; d += 256) {
        float xv = x[d];
        const float* w = Wg + (size_t)d * E_;
#pragma unroll
        for (int e = 0; e < E_; e++) acc[e] += xv * w[e];
    }
    __shared__ float red[E_][256];
#pragma unroll
    for (int e = 0; e < E_; e++) red[e][tid] = acc[e];
    __syncthreads();
    for (int s = 128; s > 0; s >>= 1) {
        if (tid < s)
#pragma unroll
            for (int e = 0; e < E_; e++) red[e][tid] += red[e][tid + s];
        __syncthreads();
    }
    if (tid == 0) {
        float gate[E_], sc[E_];
#pragma unroll
        for (int e = 0; e < E_; e++) { gate[e] = red[e][0] + bg[e]; sc[e] = gate[e] + eb[e]; }
        int i0 = 0;
        for (int e = 1; e < E_; e++) if (sc[e] > sc[i0]) i0 = e;
        int i1 = -1;
        for (int e = 0; e < E_; e++) {
            if (e == i0) continue;
            if (i1 < 0 || sc[e] > sc[i1]) i1 = e;
        }
        float r0 = gate[i0], r1 = gate[i1];
        float m = fmaxf(r0, r1);
        float e0 = expf(r0 - m), e1 = expf(r1 - m);
        float inv = 1.f / (e0 + e1);
        g_idx[t * 2] = i0; g_idx[t * 2 + 1] = i1;
        g_gw[t * 2] = e0 * inv; g_gw[t * 2 + 1] = e1 * inv;
        atomicAdd(&g_count[i0], 1);
        atomicAdd(&g_count[i1], 1);
    }
}

__global__ void prefix_k() {
    if (blockIdx.x == 0 && threadIdx.x == 0) {
        int row = 0, nt = 0;
        for (int e = 0; e < E_; e++) {
            g_base[e] = row;
            int tiles = (g_count[e] + TILE_ - 1) / TILE_;
            for (int k = 0; k < tiles; k++) g_tile_e[nt++] = e;
            row += tiles * TILE_;
        }
    }
}

__global__ void scatter_k() {
    int s = blockIdx.x * blockDim.x + threadIdx.x;
    if (s >= NS_) return;
    int e = g_idx[s];
    int pos = atomicAdd(&g_cursor[e], 1);
    int r = g_base[e] + pos;
    g_perm[r] = s;
    g_inv[s] = r;
}

// ---------------- weight transpose + bf16 hi/lo split: [e][K][N] -> [e][N][K] ----
template <int LAYER>
__global__ void wsplit_k(const float* __restrict__ W, int K, int N) {
    __nv_bfloat16 *Wh, *Wl;
    if (LAYER == 1)      { Wh = g_w1h; Wl = g_w1l; }
    else if (LAYER == 2) { Wh = g_w2h; Wl = g_w2l; }
    else                 { Wh = g_w3h; Wl = g_w3l; }
    __shared__ float t[32][33];
    int e = blockIdx.z;
    const float* We = W + (size_t)e * K * N;
    size_t ob = (size_t)e * K * N;
    int n0 = blockIdx.x * 32, k0 = blockIdx.y * 32;
    int tx = threadIdx.x, ty = threadIdx.y;
#pragma unroll
    for (int r = 0; r < 4; r++)
        t[ty + 8 * r][tx] = We[(size_t)(k0 + ty + 8 * r) * N + n0 + tx];
    __syncthreads();
#pragma unroll
    for (int r = 0; r < 4; r++) {
        int n = ty + 8 * r;
        float v = t[tx][n];
        __nv_bfloat16 h = __float2bfloat16(v);
        __nv_bfloat16 l = __float2bfloat16(v - __bfloat162float(h));
        size_t o = ob + (size_t)(n0 + n) * K + k0 + tx;
        Wh[o] = h; Wl[o] = l;
    }
}

// ---------------- x_expert fp32 -> bf16 hi/lo split ----------------
__global__ void xsplit_k(const float* __restrict__ x) {
    size_t i = ((size_t)blockIdx.x * 256 + threadIdx.x) * 4;
    float4 v = *(const float4*)(x + i);
    __nv_bfloat162 h0 = __floats2bfloat162_rn(v.x, v.y);
    __nv_bfloat162 h1 = __floats2bfloat162_rn(v.z, v.w);
    __nv_bfloat162 l0 = __floats2bfloat162_rn(v.x - __bfloat162float(h0.x),
                                              v.y - __bfloat162float(h0.y));
    __nv_bfloat162 l1 = __floats2bfloat162_rn(v.z - __bfloat162float(h1.x),
                                              v.w - __bfloat162float(h1.y));
    uint2 hh = make_uint2(*(uint32_t*)&h0, *(uint32_t*)&h1);
    uint2 ll = make_uint2(*(uint32_t*)&l0, *(uint32_t*)&l1);
    *(uint2*)(g_xh + i) = hh;
    *(uint2*)(g_xl + i) = ll;
}

// ---------------- HMMA GEMM: 128x128 CTA, BK=32, 4-stage cp.async, ldmatrix ----
// stage layout (rows padded to 80B): Ah @0, Al @R, Bh @2R, Bl @3R, R = 128*80
#define ROWB   80
#define REGION 10240
#define STAGE  (4 * REGION)
#define NSTG   4
#define SMEM_GEMM (NSTG * STAGE)   // 163840

template <int LAYER, int Kd, int Nd>
__global__ void __launch_bounds__(256, 1)
mma_gemm_k(const float* __restrict__ Ball) {
    extern __shared__ __align__(128) char smem[];
    int rt = blockIdx.y, ct = blockIdx.x;
    int e = g_tile_e[rt];
    if (e < 0) return;

    const __nv_bfloat16 *Wh, *Wl, *Ah, *Al;
    if (LAYER == 1)      { Wh = g_w1h; Wl = g_w1l; Ah = g_xh;  Al = g_xl;  }
    else if (LAYER == 2) { Wh = g_w2h; Wl = g_w2l; Ah = g_a1h; Al = g_a1l; }
    else                 { Wh = g_w3h; Wl = g_w3l; Ah = g_a2h; Al = g_a2l; }

    int row0 = rt * 128, col0 = ct * 128;
    const float* bias = Ball + (size_t)e * Nd;

    int tid = threadIdx.x, wid = tid >> 5, lid = tid & 31;
    int g = lid >> 2, t = lid & 3;
    int wm = wid & 1, wn = wid >> 1;
    int m_base = wm * 64, n_base = wn * 32;

    // ---- fill mapping ----
    int arow = tid >> 1, half = tid & 1;
    const __nv_bfloat16 *Arh, *Arl;
    uint32_t asz = 16;
    if (LAYER == 1) {
        int slot = g_perm[row0 + arow];
        if (slot >= 0) {
            Arh = Ah + (size_t)(slot >> 1) * Kd;
            Arl = Al + (size_t)(slot >> 1) * Kd;
        } else { Arh = Ah; Arl = Al; asz = 0; }
    } else {
        Arh = Ah + (size_t)(row0 + arow) * Kd;
        Arl = Al + (size_t)(row0 + arow) * Kd;
    }
    const __nv_bfloat16* Brh = Wh + (size_t)e * Nd * Kd + (size_t)(col0 + arow) * Kd;
    const __nv_bfloat16* Brl = Wl + (size_t)e * Nd * Kd + (size_t)(col0 + arow) * Kd;

    uint32_t sbase = smem_u32(smem);
    uint32_t foff = (uint32_t)arow * ROWB + half * 32;

    float acc[4][4][4];
#pragma unroll
    for (int mt = 0; mt < 4; mt++)
#pragma unroll
        for (int nt = 0; nt < 4; nt++)
#pragma unroll
            for (int q = 0; q < 4; q++) acc[mt][nt][q] = 0.f;

    constexpr int KC = Kd / 32;

    auto fill = [&](int kc) {
        uint32_t dst = sbase + (uint32_t)(kc & (NSTG - 1)) * STAGE + foff;
        int k0 = kc * 32;
        const __nv_bfloat16* s;
        s = Arh + k0 + half * 16;
        CP16Z(dst, s, asz); CP16Z(dst + 16, s + 8, asz);
        s = Arl + k0 + half * 16;
        CP16Z(dst + REGION, s, asz); CP16Z(dst + REGION + 16, s + 8, asz);
        s = Brh + k0 + half * 16;
        CP16(dst + 2 * REGION, s); CP16(dst + 2 * REGION + 16, s + 8);
        s = Brl + k0 + half * 16;
        CP16(dst + 3 * REGION, s); CP16(dst + 3 * REGION + 16, s + 8);
    };

    fill(0); CP_COMMIT();
    fill(1); CP_COMMIT();
    fill(2); CP_COMMIT();

    uint32_t lrow = lid & 15;
    uint32_t lhalf = (lid >> 4) * 16;

    for (int kc = 0; kc < KC; kc++) {
        CP_WAIT2();
        __syncthreads();
        if (kc + 3 < KC) fill(kc + 3);
        CP_COMMIT();

        uint32_t st = sbase + (uint32_t)(kc & (NSTG - 1)) * STAGE;
#pragma unroll
        for (int ks = 0; ks < 2; ks++) {
            uint32_t koff = (uint32_t)ks * 32 + lhalf;
            uint32_t ah[4][4], al[4][4], bh[2][4], bl[2][4];
#pragma unroll
            for (int mt = 0; mt < 4; mt++) {
                uint32_t a = st + (uint32_t)(m_base + mt * 16 + lrow) * ROWB + koff;
                ldm_x4(ah[mt], a);
                ldm_x4(al[mt], a + REGION);
            }
#pragma unroll
            for (int p = 0; p < 2; p++) {
                uint32_t b = st + 2 * REGION + (uint32_t)(n_base + p * 16 + lrow) * ROWB + koff;
                ldm_x4(bh[p], b);
                ldm_x4(bl[p], b + REGION);
            }
#pragma unroll
            for (int mt = 0; mt < 4; mt++)
#pragma unroll
                for (int p = 0; p < 2; p++) {
                    mma16816(acc[mt][2 * p],     ah[mt], bh[p][0], bh[p][2]);
                    mma16816(acc[mt][2 * p],     al[mt], bh[p][0], bh[p][2]);
                    mma16816(acc[mt][2 * p],     ah[mt], bl[p][0], bl[p][2]);
                    mma16816(acc[mt][2 * p + 1], ah[mt], bh[p][1], bh[p][3]);
                    mma16816(acc[mt][2 * p + 1], al[mt], bh[p][1], bh[p][3]);
                    mma16816(acc[mt][2 * p + 1], ah[mt], bl[p][1], bl[p][3]);
                }
        }
    }

    // ---- epilogue ----
    __nv_bfloat16 *Oh = nullptr, *Ol = nullptr;
    if (LAYER == 1)      { Oh = g_a1h; Ol = g_a1l; }
    else if (LAYER == 2) { Oh = g_a2h; Ol = g_a2l; }

#pragma unroll
    for (int mt = 0; mt < 4; mt++) {
        int rA = row0 + m_base + mt * 16 + g;
#pragma unroll
        for (int nt = 0; nt < 4; nt++) {
            int col = col0 + n_base + nt * 8 + t * 2;
            float2 bv = *(const float2*)(bias + col);
            float2 o0, o1;
            o0.x = acc[mt][nt][0] + bv.x; o0.y = acc[mt][nt][1] + bv.y;
            o1.x = acc[mt][nt][2] + bv.x; o1.y = acc[mt][nt][3] + bv.y;
            if (LAYER < 3) {
                o0.x = fmaxf(o0.x, 0.f); o0.y = fmaxf(o0.y, 0.f);
                o1.x = fmaxf(o1.x, 0.f); o1.y = fmaxf(o1.y, 0.f);
                __nv_bfloat162 h0 = __floats2bfloat162_rn(o0.x, o0.y);
                __nv_bfloat162 l0 = __floats2bfloat162_rn(o0.x - __bfloat162float(h0.x),
                                                          o0.y - __bfloat162float(h0.y));
                __nv_bfloat162 h1 = __floats2bfloat162_rn(o1.x, o1.y);
                __nv_bfloat162 l1 = __floats2bfloat162_rn(o1.x - __bfloat162float(h1.x),
                                                          o1.y - __bfloat162float(h1.y));
                size_t p0 = (size_t)rA * Nd + col;
                size_t p1 = (size_t)(rA + 8) * Nd + col;
                *(uint32_t*)(Oh + p0) = *(uint32_t*)&h0;
                *(uint32_t*)(Ol + p0) = *(uint32_t*)&l0;
                *(uint32_t*)(Oh + p1) = *(uint32_t*)&h1;
                *(uint32_t*)(Ol + p1) = *(uint32_t*)&l1;
            } else {
                *(float2*)(g_or + (size_t)rA * Nd + col)       = o0;
                *(float2*)(g_or + (size_t)(rA + 8) * Nd + col) = o1;
            }
        }
    }
}

// ---------------- combine ----------------
__global__ void combine_k(float* __restrict__ out) {
    int t = blockIdx.x, c = threadIdx.x;
    int r0 = g_inv[t * 2], r1 = g_inv[t * 2 + 1];
    float w0 = g_gw[t * 2], w1 = g_gw[t * 2 + 1];
    const float4* a = (const float4*)(g_or + (size_t)r0 * DO_);
    const float4* b = (const float4*)(g_or + (size_t)r1 * DO_);
    float4 va = a[c], vb = b[c], o;
    o.x = w0 * va.x + w1 * vb.x;
    o.y = w0 * va.y + w1 * vb.y;
    o.z = w0 * va.z + w1 * vb.z;
    o.w = w0 * va.w + w1 * vb.w;
    ((float4*)(out + (size_t)t * DO_))[c] = o;
}

__global__ void idxout_k(float* __restrict__ dst, int n) {
    int i = blockIdx.x * blockDim.x + threadIdx.x;
    if (i < n) dst[i] = (float)g_idx[i];
}

// ---------------- launch ----------------
extern "C" void kernel_launch(void* const* d_in, const int* in_sizes, int n_in,
                              void* d_out, int out_size) {
    (void)in_sizes; (void)n_in;
    const float* xr = (const float*)d_in[0];
    const float* xe = (const float*)d_in[1];
    const float* Wg = (const float*)d_in[2];
    const float* bg = (const float*)d_in[3];
    const float* eb = (const float*)d_in[4];
    const float* W1 = (const float*)d_in[5];
    const float* b1 = (const float*)d_in[6];
    const float* W2 = (const float*)d_in[7];
    const float* b2 = (const float*)d_in[8];
    const float* W3 = (const float*)d_in[9];
    const float* b3 = (const float*)d_in[10];
    float* out = (float*)d_out;

    cudaFuncSetAttribute(mma_gemm_k<1, DI_, H1_>, cudaFuncAttributeMaxDynamicSharedMemorySize, SMEM_GEMM);
    cudaFuncSetAttribute(mma_gemm_k<2, H1_, H2_>, cudaFuncAttributeMaxDynamicSharedMemorySize, SMEM_GEMM);
    cudaFuncSetAttribute(mma_gemm_k<3, H2_, DO_>, cudaFuncAttributeMaxDynamicSharedMemorySize, SMEM_GEMM);

    init_k<<<(MAXROWS_ + 255) / 256, 256>>>();
    router_k<<<B_, 256>>>(xr, Wg, bg, eb);
    xsplit_k<<<(B_ * DI_ / 4) / 256, 256>>>(xe);

    dim3 wt(32, 8);
    wsplit_k<1><<<dim3(H1_ / 32, DI_ / 32, E_), wt>>>(W1, DI_, H1_);
    wsplit_k<2><<<dim3(H2_ / 32, H1_ / 32, E_), wt>>>(W2, H1_, H2_);
    wsplit_k<3><<<dim3(DO_ / 32, H2_ / 32, E_), wt>>>(W3, H2_, DO_);

    prefix_k<<<1, 1>>>();
    scatter_k<<<NS_ / 256, 256>>>();

    mma_gemm_k<1, DI_, H1_><<<dim3(H1_ / 128, MAXTILES_), 256, SMEM_GEMM>>>(b1);
    mma_gemm_k<2, H1_, H2_><<<dim3(H2_ / 128, MAXTILES_), 256, SMEM_GEMM>>>(b2);
    mma_gemm_k<3, H2_, DO_><<<dim3(DO_ / 128, MAXTILES_), 256, SMEM_GEMM>>>(b3);

    combine_k<<<B_, 256>>>(out);

    int tail = out_size - B_ * DO_;
    if (tail > 0) {
        int n = tail < NS_ ? tail : NS_;
        idxout_k<<<(n + 255) / 256, 256>>>(out + (size_t)B_ * DO_, n);
    }
}

// round 6
// speedup vs baseline: 2.3215x; 1.4399x over previous
#include <cuda_runtime.h>
#include <cuda_fp16.h>
#include <math.h>
#include <stdint.h>

// ---------------- problem constants ----------------
#define B_    2048
#define DR_   1024
#define DI_   1024
#define DO_   1024
#define E_    8
#define TOPK_ 2
#define H1_   2048
#define H2_   2048
#define NS_   (B_ * TOPK_)
#define TILE_ 128
#define MAXROWS_ (NS_ + E_ * TILE_)   // 5120
#define MAXTILES_ (MAXROWS_ / TILE_)  // 40

// ---------------- device scratch ----------------
__device__ float g_or[MAXROWS_ * (size_t)DO_];
__device__ int   g_perm[MAXROWS_];
__device__ int   g_inv[NS_];
__device__ float g_gw[NS_];
__device__ int   g_idx[NS_];
__device__ int   g_count[E_];
__device__ int   g_cursor[E_];
__device__ int   g_base[E_];
__device__ int   g_tile_e[MAXTILES_];

// fp16 transposed weights: [e][N][K]
__device__ __half g_w1[(size_t)E_ * H1_ * DI_];
__device__ __half g_w2[(size_t)E_ * H2_ * H1_];
__device__ __half g_w3[(size_t)E_ * DO_ * H2_];

// fp16 hi/lo split activations
__device__ __half g_xh[(size_t)B_ * DI_];
__device__ __half g_xl[(size_t)B_ * DI_];
__device__ __half g_a1h[MAXROWS_ * (size_t)H1_];
__device__ __half g_a1l[MAXROWS_ * (size_t)H1_];
__device__ __half g_a2h[MAXROWS_ * (size_t)H2_];
__device__ __half g_a2l[MAXROWS_ * (size_t)H2_];

// ---------------- PTX helpers ----------------
__device__ __forceinline__ uint32_t smem_u32(const void* p) {
    uint32_t a;
    asm("{ .reg .u64 t; cvta.to.shared.u64 t, %1; cvt.u32.u64 %0, t; }" : "=r"(a) : "l"(p));
    return a;
}
#define CP16(dst, src) \
    asm volatile("cp.async.cg.shared.global [%0], [%1], 16;" :: "r"(dst), "l"(src))
#define CP16Z(dst, src, n) \
    asm volatile("cp.async.cg.shared.global [%0], [%1], 16, %2;" :: "r"(dst), "l"(src), "r"(n))
#define CP_COMMIT() asm volatile("cp.async.commit_group;" ::: "memory")
#define CP_WAIT1()  asm volatile("cp.async.wait_group 1;" ::: "memory")

__device__ __forceinline__ void ldm_x4(uint32_t* r, uint32_t addr) {
    asm volatile("ldmatrix.sync.aligned.m8n8.x4.shared.b16 {%0,%1,%2,%3}, [%4];"
                 : "=r"(r[0]), "=r"(r[1]), "=r"(r[2]), "=r"(r[3]) : "r"(addr));
}
__device__ __forceinline__ void mma16816(float* d, const uint32_t* a, uint32_t b0, uint32_t b1) {
    asm volatile(
        "mma.sync.aligned.m16n8k16.row.col.f32.f16.f16.f32 "
        "{%0,%1,%2,%3}, {%4,%5,%6,%7}, {%8,%9}, {%0,%1,%2,%3};"
        : "+f"(d[0]), "+f"(d[1]), "+f"(d[2]), "+f"(d[3])
        : "r"(a[0]), "r"(a[1]), "r"(a[2]), "r"(a[3]), "r"(b0), "r"(b1));
}

// ---------------- init / router / prefix / scatter ----------------
__global__ void init_k() {
    int i = blockIdx.x * blockDim.x + threadIdx.x;
    if (i < E_) { g_count[i] = 0; g_cursor[i] = 0; }
    if (i < MAXTILES_) g_tile_e[i] = -1;
    if (i < MAXROWS_) g_perm[i] = -1;
}

__global__ void router_k(const float* __restrict__ xr, const float* __restrict__ Wg,
                         const float* __restrict__ bg, const float* __restrict__ eb) {
    int t = blockIdx.x, tid = threadIdx.x;
    const float* x = xr + (size_t)t * DR_;
    float acc[E_];
#pragma unroll
    for (int e = 0; e < E_; e++) acc[e] = 0.f;
    for (int d = tid; d < DR_; d += 256) {
        float xv = x[d];
        const float* w = Wg + (size_t)d * E_;
#pragma unroll
        for (int e = 0; e < E_; e++) acc[e] += xv * w[e];
    }
    __shared__ float red[E_][256];
#pragma unroll
    for (int e = 0; e < E_; e++) red[e][tid] = acc[e];
    __syncthreads();
    for (int s = 128; s > 0; s >>= 1) {
        if (tid < s)
#pragma unroll
            for (int e = 0; e < E_; e++) red[e][tid] += red[e][tid + s];
        __syncthreads();
    }
    if (tid == 0) {
        float gate[E_], sc[E_];
#pragma unroll
        for (int e = 0; e < E_; e++) { gate[e] = red[e][0] + bg[e]; sc[e] = gate[e] + eb[e]; }
        int i0 = 0;
        for (int e = 1; e < E_; e++) if (sc[e] > sc[i0]) i0 = e;
        int i1 = -1;
        for (int e = 0; e < E_; e++) {
            if (e == i0) continue;
            if (i1 < 0 || sc[e] > sc[i1]) i1 = e;
        }
        float r0 = gate[i0], r1 = gate[i1];
        float m = fmaxf(r0, r1);
        float e0 = expf(r0 - m), e1 = expf(r1 - m);
        float inv = 1.f / (e0 + e1);
        g_idx[t * 2] = i0; g_idx[t * 2 + 1] = i1;
        g_gw[t * 2] = e0 * inv; g_gw[t * 2 + 1] = e1 * inv;
        atomicAdd(&g_count[i0], 1);
        atomicAdd(&g_count[i1], 1);
    }
}

__global__ void prefix_k() {
    if (blockIdx.x == 0 && threadIdx.x == 0) {
        int row = 0, nt = 0;
        for (int e = 0; e < E_; e++) {
            g_base[e] = row;
            int tiles = (g_count[e] + TILE_ - 1) / TILE_;
            for (int k = 0; k < tiles; k++) g_tile_e[nt++] = e;
            row += tiles * TILE_;
        }
    }
}

__global__ void scatter_k() {
    int s = blockIdx.x * blockDim.x + threadIdx.x;
    if (s >= NS_) return;
    int e = g_idx[s];
    int pos = atomicAdd(&g_cursor[e], 1);
    int r = g_base[e] + pos;
    g_perm[r] = s;
    g_inv[s] = r;
}

// ---------------- weight transpose + fp16 round: [e][K][N] -> [e][N][K] ----
template <int LAYER>
__global__ void wsplit_k(const float* __restrict__ W, int K, int N) {
    __half* Wd;
    if (LAYER == 1)      Wd = g_w1;
    else if (LAYER == 2) Wd = g_w2;
    else                 Wd = g_w3;
    __shared__ float t[32][33];
    int e = blockIdx.z;
    const float* We = W + (size_t)e * K * N;
    size_t ob = (size_t)e * K * N;
    int n0 = blockIdx.x * 32, k0 = blockIdx.y * 32;
    int tx = threadIdx.x, ty = threadIdx.y;
#pragma unroll
    for (int r = 0; r < 4; r++)
        t[ty + 8 * r][tx] = We[(size_t)(k0 + ty + 8 * r) * N + n0 + tx];
    __syncthreads();
#pragma unroll
    for (int r = 0; r < 4; r++) {
        int n = ty + 8 * r;
        Wd[ob + (size_t)(n0 + n) * K + k0 + tx] = __float2half_rn(t[tx][n]);
    }
}

// ---------------- x_expert fp32 -> fp16 hi/lo split ----------------
__global__ void xsplit_k(const float* __restrict__ x) {
    size_t i = ((size_t)blockIdx.x * 256 + threadIdx.x) * 4;
    float4 v = *(const float4*)(x + i);
    __half2 h0 = __floats2half2_rn(v.x, v.y);
    __half2 h1 = __floats2half2_rn(v.z, v.w);
    __half2 l0 = __floats2half2_rn(v.x - __half2float(h0.x), v.y - __half2float(h0.y));
    __half2 l1 = __floats2half2_rn(v.z - __half2float(h1.x), v.w - __half2float(h1.y));
    *(uint2*)(g_xh + i) = make_uint2(*(uint32_t*)&h0, *(uint32_t*)&h1);
    *(uint2*)(g_xl + i) = make_uint2(*(uint32_t*)&l0, *(uint32_t*)&l1);
}

// ---------------- HMMA GEMM: 128x128 CTA, BK=32, 3-stage cp.async, fp16 x2 ----
// stage regions (rows padded to 80B): Ah @0, Al @R, W @2R, R = 128*80
#define ROWB   80
#define REGION 10240
#define STAGE  (3 * REGION)
#define NSTG   3
#define SMEM_GEMM (NSTG * STAGE)   // 92160 -> 2 CTAs/SM

template <int LAYER, int Kd, int Nd>
__global__ void __launch_bounds__(256, 2)
mma_gemm_k(const float* __restrict__ Ball) {
    extern __shared__ __align__(128) char smem[];
    int rt = blockIdx.y, ct = blockIdx.x;
    int e = g_tile_e[rt];
    if (e < 0) return;

    const __half *Wt, *Ah, *Al;
    if (LAYER == 1)      { Wt = g_w1; Ah = g_xh;  Al = g_xl;  }
    else if (LAYER == 2) { Wt = g_w2; Ah = g_a1h; Al = g_a1l; }
    else                 { Wt = g_w3; Ah = g_a2h; Al = g_a2l; }

    int row0 = rt * 128, col0 = ct * 128;
    const float* bias = Ball + (size_t)e * Nd;

    int tid = threadIdx.x, wid = tid >> 5, lid = tid & 31;
    int g = lid >> 2, t = lid & 3;
    int wm = wid & 1, wn = wid >> 1;
    int m_base = wm * 64, n_base = wn * 32;

    // ---- fill mapping ----
    int arow = tid >> 1, half = tid & 1;
    const __half *Arh, *Arl;
    uint32_t asz = 16;
    if (LAYER == 1) {
        int slot = g_perm[row0 + arow];
        if (slot >= 0) {
            Arh = Ah + (size_t)(slot >> 1) * Kd;
            Arl = Al + (size_t)(slot >> 1) * Kd;
        } else { Arh = Ah; Arl = Al; asz = 0; }
    } else {
        Arh = Ah + (size_t)(row0 + arow) * Kd;
        Arl = Al + (size_t)(row0 + arow) * Kd;
    }
    const __half* Br = Wt + (size_t)e * Nd * Kd + (size_t)(col0 + arow) * Kd;

    uint32_t sbase = smem_u32(smem);
    uint32_t foff = (uint32_t)arow * ROWB + half * 32;

    float acc[4][4][4];
#pragma unroll
    for (int mt = 0; mt < 4; mt++)
#pragma unroll
        for (int nt = 0; nt < 4; nt++)
#pragma unroll
            for (int q = 0; q < 4; q++) acc[mt][nt][q] = 0.f;

    constexpr int KC = Kd / 32;

    auto fill = [&](int kc) {
        uint32_t dst = sbase + (uint32_t)(kc % NSTG) * STAGE + foff;
        int k0 = kc * 32;
        const __half* s;
        s = Arh + k0 + half * 16;
        CP16Z(dst, s, asz); CP16Z(dst + 16, s + 8, asz);
        s = Arl + k0 + half * 16;
        CP16Z(dst + REGION, s, asz); CP16Z(dst + REGION + 16, s + 8, asz);
        s = Br + k0 + half * 16;
        CP16(dst + 2 * REGION, s); CP16(dst + 2 * REGION + 16, s + 8);
    };

    fill(0); CP_COMMIT();
    fill(1); CP_COMMIT();

    uint32_t lrow = lid & 15;
    uint32_t lhalf = (lid >> 4) * 16;

    for (int kc = 0; kc < KC; kc++) {
        CP_WAIT1();
        __syncthreads();
        if (kc + 2 < KC) fill(kc + 2);
        CP_COMMIT();

        uint32_t st = sbase + (uint32_t)(kc % NSTG) * STAGE;
#pragma unroll
        for (int ks = 0; ks < 2; ks++) {
            uint32_t koff = (uint32_t)ks * 32 + lhalf;
            uint32_t ah[4][4], al[4][4], bh[2][4];
#pragma unroll
            for (int mt = 0; mt < 4; mt++) {
                uint32_t a = st + (uint32_t)(m_base + mt * 16 + lrow) * ROWB + koff;
                ldm_x4(ah[mt], a);
                ldm_x4(al[mt], a + REGION);
            }
#pragma unroll
            for (int p = 0; p < 2; p++) {
                uint32_t b = st + 2 * REGION + (uint32_t)(n_base + p * 16 + lrow) * ROWB + koff;
                ldm_x4(bh[p], b);
            }
#pragma unroll
            for (int mt = 0; mt < 4; mt++)
#pragma unroll
                for (int p = 0; p < 2; p++) {
                    mma16816(acc[mt][2 * p],     ah[mt], bh[p][0], bh[p][2]);
                    mma16816(acc[mt][2 * p],     al[mt], bh[p][0], bh[p][2]);
                    mma16816(acc[mt][2 * p + 1], ah[mt], bh[p][1], bh[p][3]);
                    mma16816(acc[mt][2 * p + 1], al[mt], bh[p][1], bh[p][3]);
                }
        }
    }

    // ---- epilogue ----
    __half *Oh = nullptr, *Ol = nullptr;
    if (LAYER == 1)      { Oh = g_a1h; Ol = g_a1l; }
    else if (LAYER == 2) { Oh = g_a2h; Ol = g_a2l; }

#pragma unroll
    for (int mt = 0; mt < 4; mt++) {
        int rA = row0 + m_base + mt * 16 + g;
#pragma unroll
        for (int nt = 0; nt < 4; nt++) {
            int col = col0 + n_base + nt * 8 + t * 2;
            float2 bv = *(const float2*)(bias + col);
            float2 o0, o1;
            o0.x = acc[mt][nt][0] + bv.x; o0.y = acc[mt][nt][1] + bv.y;
            o1.x = acc[mt][nt][2] + bv.x; o1.y = acc[mt][nt][3] + bv.y;
            if (LAYER < 3) {
                o0.x = fmaxf(o0.x, 0.f); o0.y = fmaxf(o0.y, 0.f);
                o1.x = fmaxf(o1.x, 0.f); o1.y = fmaxf(o1.y, 0.f);
                __half2 h0 = __floats2half2_rn(o0.x, o0.y);
                __half2 l0 = __floats2half2_rn(o0.x - __half2float(h0.x),
                                               o0.y - __half2float(h0.y));
                __half2 h1 = __floats2half2_rn(o1.x, o1.y);
                __half2 l1 = __floats2half2_rn(o1.x - __half2float(h1.x),
                                               o1.y - __half2float(h1.y));
                size_t p0 = (size_t)rA * Nd + col;
                size_t p1 = (size_t)(rA + 8) * Nd + col;
                *(uint32_t*)(Oh + p0) = *(uint32_t*)&h0;
                *(uint32_t*)(Ol + p0) = *(uint32_t*)&l0;
                *(uint32_t*)(Oh + p1) = *(uint32_t*)&h1;
                *(uint32_t*)(Ol + p1) = *(uint32_t*)&l1;
            } else {
                *(float2*)(g_or + (size_t)rA * Nd + col)       = o0;
                *(float2*)(g_or + (size_t)(rA + 8) * Nd + col) = o1;
            }
        }
    }
}

// ---------------- combine ----------------
__global__ void combine_k(float* __restrict__ out) {
    int t = blockIdx.x, c = threadIdx.x;
    int r0 = g_inv[t * 2], r1 = g_inv[t * 2 + 1];
    float w0 = g_gw[t * 2], w1 = g_gw[t * 2 + 1];
    const float4* a = (const float4*)(g_or + (size_t)r0 * DO_);
    const float4* b = (const float4*)(g_or + (size_t)r1 * DO_);
    float4 va = a[c], vb = b[c], o;
    o.x = w0 * va.x + w1 * vb.x;
    o.y = w0 * va.y + w1 * vb.y;
    o.z = w0 * va.z + w1 * vb.z;
    o.w = w0 * va.w + w1 * vb.w;
    ((float4*)(out + (size_t)t * DO_))[c] = o;
}

__global__ void idxout_k(float* __restrict__ dst, int n) {
    int i = blockIdx.x * blockDim.x + threadIdx.x;
    if (i < n) dst[i] = (float)g_idx[i];
}

// ---------------- launch ----------------
extern "C" void kernel_launch(void* const* d_in, const int* in_sizes, int n_in,
                              void* d_out, int out_size) {
    (void)in_sizes; (void)n_in;
    const float* xr = (const float*)d_in[0];
    const float* xe = (const float*)d_in[1];
    const float* Wg = (const float*)d_in[2];
    const float* bg = (const float*)d_in[3];
    const float* eb = (const float*)d_in[4];
    const float* W1 = (const float*)d_in[5];
    const float* b1 = (const float*)d_in[6];
    const float* W2 = (const float*)d_in[7];
    const float* b2 = (const float*)d_in[8];
    const float* W3 = (const float*)d_in[9];
    const float* b3 = (const float*)d_in[10];
    float* out = (float*)d_out;

    cudaFuncSetAttribute(mma_gemm_k<1, DI_, H1_>, cudaFuncAttributeMaxDynamicSharedMemorySize, SMEM_GEMM);
    cudaFuncSetAttribute(mma_gemm_k<2, H1_, H2_>, cudaFuncAttributeMaxDynamicSharedMemorySize, SMEM_GEMM);
    cudaFuncSetAttribute(mma_gemm_k<3, H2_, DO_>, cudaFuncAttributeMaxDynamicSharedMemorySize, SMEM_GEMM);

    init_k<<<(MAXROWS_ + 255) / 256, 256>>>();
    router_k<<<B_, 256>>>(xr, Wg, bg, eb);
    xsplit_k<<<(B_ * DI_ / 4) / 256, 256>>>(xe);

    dim3 wt(32, 8);
    wsplit_k<1><<<dim3(H1_ / 32, DI_ / 32, E_), wt>>>(W1, DI_, H1_);
    wsplit_k<2><<<dim3(H2_ / 32, H1_ / 32, E_), wt>>>(W2, H1_, H2_);
    wsplit_k<3><<<dim3(DO_ / 32, H2_ / 32, E_), wt>>>(W3, H2_, DO_);

    prefix_k<<<1, 1>>>();
    scatter_k<<<NS_ / 256, 256>>>();

    mma_gemm_k<1, DI_, H1_><<<dim3(H1_ / 128, MAXTILES_), 256, SMEM_GEMM>>>(b1);
    mma_gemm_k<2, H1_, H2_><<<dim3(H2_ / 128, MAXTILES_), 256, SMEM_GEMM>>>(b2);
    mma_gemm_k<3, H2_, DO_><<<dim3(DO_ / 128, MAXTILES_), 256, SMEM_GEMM>>>(b3);

    combine_k<<<B_, 256>>>(out);

    int tail = out_size - B_ * DO_;
    if (tail > 0) {
        int n = tail < NS_ ? tail : NS_;
        idxout_k<<<(n + 255) / 256, 256>>>(out + (size_t)B_ * DO_, n);
    }
}

// round 7
// speedup vs baseline: 3.9355x; 1.6952x over previous
#include <cuda_runtime.h>
#include <cuda_fp16.h>
#include <math.h>
#include <stdint.h>

// ---------------- problem constants ----------------
#define B_    2048
#define DR_   1024
#define DI_   1024
#define DO_   1024
#define E_    8
#define TOPK_ 2
#define H1_   2048
#define H2_   2048
#define NS_   (B_ * TOPK_)
#define TILE_ 128
#define MAXROWS_ (NS_ + E_ * TILE_)   // 5120
#define MAXTILES_ (MAXROWS_ / TILE_)  // 40

// ---------------- device scratch ----------------
__device__ float g_or[MAXROWS_ * (size_t)DO_];
__device__ int   g_perm[MAXROWS_];
__device__ int   g_inv[NS_];
__device__ float g_gw[NS_];
__device__ int   g_idx[NS_];
__device__ int   g_count[E_];
__device__ int   g_cursor[E_];
__device__ int   g_base[E_];
__device__ int   g_tile_e[MAXTILES_];

// fp16 transposed weights: [e][N][K]
__device__ __half g_w1[(size_t)E_ * H1_ * DI_];
__device__ __half g_w2[(size_t)E_ * H2_ * H1_];
__device__ __half g_w3[(size_t)E_ * DO_ * H2_];

// fp16 activations
__device__ __half g_x[(size_t)B_ * DI_];
__device__ __half g_a1[MAXROWS_ * (size_t)H1_];
__device__ __half g_a2[MAXROWS_ * (size_t)H2_];

// ---------------- PTX helpers ----------------
__device__ __forceinline__ uint32_t smem_u32(const void* p) {
    uint32_t a;
    asm("{ .reg .u64 t; cvta.to.shared.u64 t, %1; cvt.u32.u64 %0, t; }" : "=r"(a) : "l"(p));
    return a;
}
#define CP16(dst, src) \
    asm volatile("cp.async.cg.shared.global [%0], [%1], 16;" :: "r"(dst), "l"(src))
#define CP16Z(dst, src, n) \
    asm volatile("cp.async.cg.shared.global [%0], [%1], 16, %2;" :: "r"(dst), "l"(src), "r"(n))
#define CP_COMMIT() asm volatile("cp.async.commit_group;" ::: "memory")
#define CP_WAIT2()  asm volatile("cp.async.wait_group 2;" ::: "memory")

__device__ __forceinline__ void ldm_x4(uint32_t* r, uint32_t addr) {
    asm volatile("ldmatrix.sync.aligned.m8n8.x4.shared.b16 {%0,%1,%2,%3}, [%4];"
                 : "=r"(r[0]), "=r"(r[1]), "=r"(r[2]), "=r"(r[3]) : "r"(addr));
}
__device__ __forceinline__ void mma16816(float* d, const uint32_t* a, uint32_t b0, uint32_t b1) {
    asm volatile(
        "mma.sync.aligned.m16n8k16.row.col.f32.f16.f16.f32 "
        "{%0,%1,%2,%3}, {%4,%5,%6,%7}, {%8,%9}, {%0,%1,%2,%3};"
        : "+f"(d[0]), "+f"(d[1]), "+f"(d[2]), "+f"(d[3])
        : "r"(a[0]), "r"(a[1]), "r"(a[2]), "r"(a[3]), "r"(b0), "r"(b1));
}

// ---------------- init / router / prefix / scatter ----------------
__global__ void init_k() {
    int i = blockIdx.x * blockDim.x + threadIdx.x;
    if (i < E_) { g_count[i] = 0; g_cursor[i] = 0; }
    if (i < MAXTILES_) g_tile_e[i] = -1;
    if (i < MAXROWS_) g_perm[i] = -1;
}

__global__ void router_k(const float* __restrict__ xr, const float* __restrict__ Wg,
                         const float* __restrict__ bg, const float* __restrict__ eb) {
    int t = blockIdx.x, tid = threadIdx.x;
    const float* x = xr + (size_t)t * DR_;
    float acc[E_];
#pragma unroll
    for (int e = 0; e < E_; e++) acc[e] = 0.f;
    for (int d = tid; d < DR_; d += 256) {
        float xv = x[d];
        const float* w = Wg + (size_t)d * E_;
#pragma unroll
        for (int e = 0; e < E_; e++) acc[e] += xv * w[e];
    }
    __shared__ float red[E_][256];
#pragma unroll
    for (int e = 0; e < E_; e++) red[e][tid] = acc[e];
    __syncthreads();
    for (int s = 128; s > 0; s >>= 1) {
        if (tid < s)
#pragma unroll
            for (int e = 0; e < E_; e++) red[e][tid] += red[e][tid + s];
        __syncthreads();
    }
    if (tid == 0) {
        float gate[E_], sc[E_];
#pragma unroll
        for (int e = 0; e < E_; e++) { gate[e] = red[e][0] + bg[e]; sc[e] = gate[e] + eb[e]; }
        int i0 = 0;
        for (int e = 1; e < E_; e++) if (sc[e] > sc[i0]) i0 = e;
        int i1 = -1;
        for (int e = 0; e < E_; e++) {
            if (e == i0) continue;
            if (i1 < 0 || sc[e] > sc[i1]) i1 = e;
        }
        float r0 = gate[i0], r1 = gate[i1];
        float m = fmaxf(r0, r1);
        float e0 = expf(r0 - m), e1 = expf(r1 - m);
        float inv = 1.f / (e0 + e1);
        g_idx[t * 2] = i0; g_idx[t * 2 + 1] = i1;
        g_gw[t * 2] = e0 * inv; g_gw[t * 2 + 1] = e1 * inv;
        atomicAdd(&g_count[i0], 1);
        atomicAdd(&g_count[i1], 1);
    }
}

__global__ void prefix_k() {
    if (blockIdx.x == 0 && threadIdx.x == 0) {
        int row = 0, nt = 0;
        for (int e = 0; e < E_; e++) {
            g_base[e] = row;
            int tiles = (g_count[e] + TILE_ - 1) / TILE_;
            for (int k = 0; k < tiles; k++) g_tile_e[nt++] = e;
            row += tiles * TILE_;
        }
    }
}

__global__ void scatter_k() {
    int s = blockIdx.x * blockDim.x + threadIdx.x;
    if (s >= NS_) return;
    int e = g_idx[s];
    int pos = atomicAdd(&g_cursor[e], 1);
    int r = g_base[e] + pos;
    g_perm[r] = s;
    g_inv[s] = r;
}

// ---------------- weight transpose + fp16 round: [e][K][N] -> [e][N][K] ----
template <int LAYER>
__global__ void wsplit_k(const float* __restrict__ W, int K, int N) {
    __half* Wd;
    if (LAYER == 1)      Wd = g_w1;
    else if (LAYER == 2) Wd = g_w2;
    else                 Wd = g_w3;
    __shared__ float t[32][33];
    int e = blockIdx.z;
    const float* We = W + (size_t)e * K * N;
    size_t ob = (size_t)e * K * N;
    int n0 = blockIdx.x * 32, k0 = blockIdx.y * 32;
    int tx = threadIdx.x, ty = threadIdx.y;
#pragma unroll
    for (int r = 0; r < 4; r++)
        t[ty + 8 * r][tx] = We[(size_t)(k0 + ty + 8 * r) * N + n0 + tx];
    __syncthreads();
#pragma unroll
    for (int r = 0; r < 4; r++) {
        int n = ty + 8 * r;
        Wd[ob + (size_t)(n0 + n) * K + k0 + tx] = __float2half_rn(t[tx][n]);
    }
}

// ---------------- x_expert fp32 -> fp16 ----------------
__global__ void xsplit_k(const float* __restrict__ x) {
    size_t i = ((size_t)blockIdx.x * 256 + threadIdx.x) * 4;
    float4 v = *(const float4*)(x + i);
    __half2 h0 = __floats2half2_rn(v.x, v.y);
    __half2 h1 = __floats2half2_rn(v.z, v.w);
    *(uint2*)(g_x + i) = make_uint2(*(uint32_t*)&h0, *(uint32_t*)&h1);
}

// ---------------- HMMA GEMM: 128x128 CTA, BK=32, 4-stage cp.async, fp16 ----
// stage regions (rows padded to 80B): A @0, W @R, R = 128*80
#define ROWB   80
#define REGION 10240
#define STAGE  (2 * REGION)
#define NSTG   4
#define SMEM_GEMM (NSTG * STAGE)   // 81920 -> 2 CTAs/SM

template <int LAYER, int Kd, int Nd>
__global__ void __launch_bounds__(256, 2)
mma_gemm_k(const float* __restrict__ Ball) {
    extern __shared__ __align__(128) char smem[];
    int rt = blockIdx.y, ct = blockIdx.x;
    int e = g_tile_e[rt];
    if (e < 0) return;

    const __half *Wt, *Ain;
    if (LAYER == 1)      { Wt = g_w1; Ain = g_x;  }
    else if (LAYER == 2) { Wt = g_w2; Ain = g_a1; }
    else                 { Wt = g_w3; Ain = g_a2; }

    int row0 = rt * 128, col0 = ct * 128;
    const float* bias = Ball + (size_t)e * Nd;

    int tid = threadIdx.x, wid = tid >> 5, lid = tid & 31;
    int g = lid >> 2, t = lid & 3;
    int wm = wid & 1, wn = wid >> 1;
    int m_base = wm * 64, n_base = wn * 32;

    // ---- fill mapping ----
    int arow = tid >> 1, half = tid & 1;
    const __half* Ar;
    uint32_t asz = 16;
    if (LAYER == 1) {
        int slot = g_perm[row0 + arow];
        if (slot >= 0) Ar = Ain + (size_t)(slot >> 1) * Kd;
        else { Ar = Ain; asz = 0; }
    } else {
        Ar = Ain + (size_t)(row0 + arow) * Kd;
    }
    const __half* Br = Wt + (size_t)e * Nd * Kd + (size_t)(col0 + arow) * Kd;

    uint32_t sbase = smem_u32(smem);
    uint32_t foff = (uint32_t)arow * ROWB + half * 32;

    float acc[4][4][4];
#pragma unroll
    for (int mt = 0; mt < 4; mt++)
#pragma unroll
        for (int nt = 0; nt < 4; nt++)
#pragma unroll
            for (int q = 0; q < 4; q++) acc[mt][nt][q] = 0.f;

    constexpr int KC = Kd / 32;

    auto fill = [&](int kc) {
        uint32_t dst = sbase + (uint32_t)(kc & (NSTG - 1)) * STAGE + foff;
        int k0 = kc * 32;
        const __half* s;
        s = Ar + k0 + half * 16;
        CP16Z(dst, s, asz); CP16Z(dst + 16, s + 8, asz);
        s = Br + k0 + half * 16;
        CP16(dst + REGION, s); CP16(dst + REGION + 16, s + 8);
    };

    fill(0); CP_COMMIT();
    fill(1); CP_COMMIT();
    fill(2); CP_COMMIT();

    uint32_t lrow = lid & 15;
    uint32_t lhalf = (lid >> 4) * 16;

    for (int kc = 0; kc < KC; kc++) {
        CP_WAIT2();
        __syncthreads();
        if (kc + 3 < KC) fill(kc + 3);
        CP_COMMIT();

        uint32_t st = sbase + (uint32_t)(kc & (NSTG - 1)) * STAGE;
#pragma unroll
        for (int ks = 0; ks < 2; ks++) {
            uint32_t koff = (uint32_t)ks * 32 + lhalf;
            uint32_t ah[4][4], bh[2][4];
#pragma unroll
            for (int mt = 0; mt < 4; mt++)
                ldm_x4(ah[mt], st + (uint32_t)(m_base + mt * 16 + lrow) * ROWB + koff);
#pragma unroll
            for (int p = 0; p < 2; p++)
                ldm_x4(bh[p], st + REGION + (uint32_t)(n_base + p * 16 + lrow) * ROWB + koff);
#pragma unroll
            for (int mt = 0; mt < 4; mt++)
#pragma unroll
                for (int p = 0; p < 2; p++) {
                    mma16816(acc[mt][2 * p],     ah[mt], bh[p][0], bh[p][2]);
                    mma16816(acc[mt][2 * p + 1], ah[mt], bh[p][1], bh[p][3]);
                }
        }
    }

    // ---- epilogue ----
    __half* Oh = nullptr;
    if (LAYER == 1)      Oh = g_a1;
    else if (LAYER == 2) Oh = g_a2;

#pragma unroll
    for (int mt = 0; mt < 4; mt++) {
        int rA = row0 + m_base + mt * 16 + g;
#pragma unroll
        for (int nt = 0; nt < 4; nt++) {
            int col = col0 + n_base + nt * 8 + t * 2;
            float2 bv = *(const float2*)(bias + col);
            float2 o0, o1;
            o0.x = acc[mt][nt][0] + bv.x; o0.y = acc[mt][nt][1] + bv.y;
            o1.x = acc[mt][nt][2] + bv.x; o1.y = acc[mt][nt][3] + bv.y;
            if (LAYER < 3) {
                o0.x = fmaxf(o0.x, 0.f); o0.y = fmaxf(o0.y, 0.f);
                o1.x = fmaxf(o1.x, 0.f); o1.y = fmaxf(o1.y, 0.f);
                __half2 h0 = __floats2half2_rn(o0.x, o0.y);
                __half2 h1 = __floats2half2_rn(o1.x, o1.y);
                *(uint32_t*)(Oh + (size_t)rA * Nd + col)       = *(uint32_t*)&h0;
                *(uint32_t*)(Oh + (size_t)(rA + 8) * Nd + col) = *(uint32_t*)&h1;
            } else {
                *(float2*)(g_or + (size_t)rA * Nd + col)       = o0;
                *(float2*)(g_or + (size_t)(rA + 8) * Nd + col) = o1;
            }
        }
    }
}

// ---------------- combine ----------------
__global__ void combine_k(float* __restrict__ out) {
    int t = blockIdx.x, c = threadIdx.x;
    int r0 = g_inv[t * 2], r1 = g_inv[t * 2 + 1];
    float w0 = g_gw[t * 2], w1 = g_gw[t * 2 + 1];
    const float4* a = (const float4*)(g_or + (size_t)r0 * DO_);
    const float4* b = (const float4*)(g_or + (size_t)r1 * DO_);
    float4 va = a[c], vb = b[c], o;
    o.x = w0 * va.x + w1 * vb.x;
    o.y = w0 * va.y + w1 * vb.y;
    o.z = w0 * va.z + w1 * vb.z;
    o.w = w0 * va.w + w1 * vb.w;
    ((float4*)(out + (size_t)t * DO_))[c] = o;
}

__global__ void idxout_k(float* __restrict__ dst, int n) {
    int i = blockIdx.x * blockDim.x + threadIdx.x;
    if (i < n) dst[i] = (float)g_idx[i];
}

// ---------------- launch ----------------
extern "C" void kernel_launch(void* const* d_in, const int* in_sizes, int n_in,
                              void* d_out, int out_size) {
    (void)in_sizes; (void)n_in;
    const float* xr = (const float*)d_in[0];
    const float* xe = (const float*)d_in[1];
    const float* Wg = (const float*)d_in[2];
    const float* bg = (const float*)d_in[3];
    const float* eb = (const float*)d_in[4];
    const float* W1 = (const float*)d_in[5];
    const float* b1 = (const float*)d_in[6];
    const float* W2 = (const float*)d_in[7];
    const float* b2 = (const float*)d_in[8];
    const float* W3 = (const float*)d_in[9];
    const float* b3 = (const float*)d_in[10];
    float* out = (float*)d_out;

    cudaFuncSetAttribute(mma_gemm_k<1, DI_, H1_>, cudaFuncAttributeMaxDynamicSharedMemorySize, SMEM_GEMM);
    cudaFuncSetAttribute(mma_gemm_k<2, H1_, H2_>, cudaFuncAttributeMaxDynamicSharedMemorySize, SMEM_GEMM);
    cudaFuncSetAttribute(mma_gemm_k<3, H2_, DO_>, cudaFuncAttributeMaxDynamicSharedMemorySize, SMEM_GEMM);

    init_k<<<(MAXROWS_ + 255) / 256, 256>>>();
    router_k<<<B_, 256>>>(xr, Wg, bg, eb);
    xsplit_k<<<(B_ * DI_ / 4) / 256, 256>>>(xe);

    dim3 wt(32, 8);
    wsplit_k<1><<<dim3(H1_ / 32, DI_ / 32, E_), wt>>>(W1, DI_, H1_);
    wsplit_k<2><<<dim3(H2_ / 32, H1_ / 32, E_), wt>>>(W2, H1_, H2_);
    wsplit_k<3><<<dim3(DO_ / 32, H2_ / 32, E_), wt>>>(W3, H2_, DO_);

    prefix_k<<<1, 1>>>();
    scatter_k<<<NS_ / 256, 256>>>();

    mma_gemm_k<1, DI_, H1_><<<dim3(H1_ / 128, MAXTILES_), 256, SMEM_GEMM>>>(b1);
    mma_gemm_k<2, H1_, H2_><<<dim3(H2_ / 128, MAXTILES_), 256, SMEM_GEMM>>>(b2);
    mma_gemm_k<3, H2_, DO_><<<dim3(DO_ / 128, MAXTILES_), 256, SMEM_GEMM>>>(b3);

    combine_k<<<B_, 256>>>(out);

    int tail = out_size - B_ * DO_;
    if (tail > 0) {
        int n = tail < NS_ ? tail : NS_;
        idxout_k<<<(n + 255) / 256, 256>>>(out + (size_t)B_ * DO_, n);
    }
}

// round 8
// speedup vs baseline: 3.9957x; 1.0153x over previous
#include <cuda_runtime.h>
#include <cuda_fp16.h>
#include <math.h>
#include <stdint.h>

// ---------------- problem constants ----------------
#define B_    2048
#define DR_   1024
#define DI_   1024
#define DO_   1024
#define E_    8
#define TOPK_ 2
#define H1_   2048
#define H2_   2048
#define NS_   (B_ * TOPK_)
#define TILE_ 128
#define MAXROWS_ (NS_ + E_ * TILE_)   // 5120
#define MAXTILES_ (MAXROWS_ / TILE_)  // 40

// ---------------- device scratch ----------------
__device__ float g_or[MAXROWS_ * (size_t)DO_];
__device__ int   g_perm[MAXROWS_];
__device__ int   g_inv[NS_];
__device__ float g_gw[NS_];
__device__ int   g_idx[NS_];
__device__ int   g_count[E_];
__device__ int   g_cursor[E_];
__device__ int   g_base[E_];
__device__ int   g_tile_e[MAXTILES_];

// fp16 transposed weights: [e][N][K]
__device__ __half g_w1[(size_t)E_ * H1_ * DI_];
__device__ __half g_w2[(size_t)E_ * H2_ * H1_];
__device__ __half g_w3[(size_t)E_ * DO_ * H2_];

// fp16 activations
__device__ __half g_x[(size_t)B_ * DI_];
__device__ __half g_a1[MAXROWS_ * (size_t)H1_];
__device__ __half g_a2[MAXROWS_ * (size_t)H2_];

// ---------------- PTX helpers ----------------
__device__ __forceinline__ uint32_t smem_u32(const void* p) {
    uint32_t a;
    asm("{ .reg .u64 t; cvta.to.shared.u64 t, %1; cvt.u32.u64 %0, t; }" : "=r"(a) : "l"(p));
    return a;
}
#define CP16(dst, src) \
    asm volatile("cp.async.cg.shared.global [%0], [%1], 16;" :: "r"(dst), "l"(src))
#define CP16Z(dst, src, n) \
    asm volatile("cp.async.cg.shared.global [%0], [%1], 16, %2;" :: "r"(dst), "l"(src), "r"(n))
#define CP_COMMIT() asm volatile("cp.async.commit_group;" ::: "memory")
#define CP_WAIT2()  asm volatile("cp.async.wait_group 2;" ::: "memory")

__device__ __forceinline__ void ldm_x4(uint32_t* r, uint32_t addr) {
    asm volatile("ldmatrix.sync.aligned.m8n8.x4.shared.b16 {%0,%1,%2,%3}, [%4];"
                 : "=r"(r[0]), "=r"(r[1]), "=r"(r[2]), "=r"(r[3]) : "r"(addr));
}
__device__ __forceinline__ void mma16816(float* d, const uint32_t* a, uint32_t b0, uint32_t b1) {
    asm volatile(
        "mma.sync.aligned.m16n8k16.row.col.f32.f16.f16.f32 "
        "{%0,%1,%2,%3}, {%4,%5,%6,%7}, {%8,%9}, {%0,%1,%2,%3};"
        : "+f"(d[0]), "+f"(d[1]), "+f"(d[2]), "+f"(d[3])
        : "r"(a[0]), "r"(a[1]), "r"(a[2]), "r"(a[3]), "r"(b0), "r"(b1));
}

// ---------------- init / router / prefix / scatter ----------------
__global__ void init_k() {
    int i = blockIdx.x * blockDim.x + threadIdx.x;
    if (i < E_) { g_count[i] = 0; g_cursor[i] = 0; }
    if (i < MAXTILES_) g_tile_e[i] = -1;
    if (i < MAXROWS_) g_perm[i] = -1;
}

__global__ void router_k(const float* __restrict__ xr, const float* __restrict__ Wg,
                         const float* __restrict__ bg, const float* __restrict__ eb) {
    int t = blockIdx.x, tid = threadIdx.x;
    const float* x = xr + (size_t)t * DR_;
    float acc[E_];
#pragma unroll
    for (int e = 0; e < E_; e++) acc[e] = 0.f;
    for (int d = tid; d < DR_; d += 256) {
        float xv = x[d];
        const float* w = Wg + (size_t)d * E_;
#pragma unroll
        for (int e = 0; e < E_; e++) acc[e] += xv * w[e];
    }
    __shared__ float red[E_][256];
#pragma unroll
    for (int e = 0; e < E_; e++) red[e][tid] = acc[e];
    __syncthreads();
    for (int s = 128; s > 0; s >>= 1) {
        if (tid < s)
#pragma unroll
            for (int e = 0; e < E_; e++) red[e][tid] += red[e][tid + s];
        __syncthreads();
    }
    if (tid == 0) {
        float gate[E_], sc[E_];
#pragma unroll
        for (int e = 0; e < E_; e++) { gate[e] = red[e][0] + bg[e]; sc[e] = gate[e] + eb[e]; }
        int i0 = 0;
        for (int e = 1; e < E_; e++) if (sc[e] > sc[i0]) i0 = e;
        int i1 = -1;
        for (int e = 0; e < E_; e++) {
            if (e == i0) continue;
            if (i1 < 0 || sc[e] > sc[i1]) i1 = e;
        }
        float r0 = gate[i0], r1 = gate[i1];
        float m = fmaxf(r0, r1);
        float e0 = expf(r0 - m), e1 = expf(r1 - m);
        float inv = 1.f / (e0 + e1);
        g_idx[t * 2] = i0; g_idx[t * 2 + 1] = i1;
        g_gw[t * 2] = e0 * inv; g_gw[t * 2 + 1] = e1 * inv;
        atomicAdd(&g_count[i0], 1);
        atomicAdd(&g_count[i1], 1);
    }
}

__global__ void prefix_k() {
    if (blockIdx.x == 0 && threadIdx.x == 0) {
        int row = 0, nt = 0;
        for (int e = 0; e < E_; e++) {
            g_base[e] = row;
            int tiles = (g_count[e] + TILE_ - 1) / TILE_;
            for (int k = 0; k < tiles; k++) g_tile_e[nt++] = e;
            row += tiles * TILE_;
        }
    }
}

__global__ void scatter_k() {
    int s = blockIdx.x * blockDim.x + threadIdx.x;
    if (s >= NS_) return;
    int e = g_idx[s];
    int pos = atomicAdd(&g_cursor[e], 1);
    int r = g_base[e] + pos;
    g_perm[r] = s;
    g_inv[s] = r;
}

// ---------------- weight transpose + fp16 round: [e][K][N] -> [e][N][K] ----
template <int LAYER>
__global__ void wsplit_k(const float* __restrict__ W, int K, int N) {
    __half* Wd;
    if (LAYER == 1)      Wd = g_w1;
    else if (LAYER == 2) Wd = g_w2;
    else                 Wd = g_w3;
    __shared__ float t[32][33];
    int e = blockIdx.z;
    const float* We = W + (size_t)e * K * N;
    size_t ob = (size_t)e * K * N;
    int n0 = blockIdx.x * 32, k0 = blockIdx.y * 32;
    int tx = threadIdx.x, ty = threadIdx.y;
#pragma unroll
    for (int r = 0; r < 4; r++)
        t[ty + 8 * r][tx] = We[(size_t)(k0 + ty + 8 * r) * N + n0 + tx];
    __syncthreads();
#pragma unroll
    for (int r = 0; r < 4; r++) {
        int n = ty + 8 * r;
        Wd[ob + (size_t)(n0 + n) * K + k0 + tx] = __float2half_rn(t[tx][n]);
    }
}

// ---------------- x_expert fp32 -> fp16 ----------------
__global__ void xsplit_k(const float* __restrict__ x) {
    size_t i = ((size_t)blockIdx.x * 256 + threadIdx.x) * 4;
    float4 v = *(const float4*)(x + i);
    __half2 h0 = __floats2half2_rn(v.x, v.y);
    __half2 h1 = __floats2half2_rn(v.z, v.w);
    *(uint2*)(g_x + i) = make_uint2(*(uint32_t*)&h0, *(uint32_t*)&h1);
}

// ---------------- HMMA GEMM: 128x128 CTA, BK=32, 4-stage cp.async, fp16 ----
// stage regions (rows padded to 80B): A @0, W @R, R = 128*80
#define ROWB   80
#define REGION 10240
#define STAGE  (2 * REGION)
#define NSTG   4
#define SMEM_GEMM (NSTG * STAGE)   // 81920 -> 2 CTAs/SM

template <int LAYER, int Kd, int Nd>
__global__ void __launch_bounds__(256, 2)
mma_gemm_k(const float* __restrict__ Ball) {
    extern __shared__ __align__(128) char smem[];
    int rt = blockIdx.y, ct = blockIdx.x;
    int e = g_tile_e[rt];
    if (e < 0) return;

    const __half *Wt, *Ain;
    if (LAYER == 1)      { Wt = g_w1; Ain = g_x;  }
    else if (LAYER == 2) { Wt = g_w2; Ain = g_a1; }
    else                 { Wt = g_w3; Ain = g_a2; }

    int row0 = rt * 128, col0 = ct * 128;
    const float* bias = Ball + (size_t)e * Nd;

    int tid = threadIdx.x, wid = tid >> 5, lid = tid & 31;
    int g = lid >> 2, t = lid & 3;
    int wm = wid & 1, wn = wid >> 1;
    int m_base = wm * 64, n_base = wn * 32;

    // ---- fill mapping ----
    int arow = tid >> 1, half = tid & 1;
    const __half* Ar;
    uint32_t asz = 16;
    if (LAYER == 1) {
        int slot = g_perm[row0 + arow];
        if (slot >= 0) Ar = Ain + (size_t)(slot >> 1) * Kd;
        else { Ar = Ain; asz = 0; }
    } else {
        Ar = Ain + (size_t)(row0 + arow) * Kd;
    }
    const __half* Br = Wt + (size_t)e * Nd * Kd + (size_t)(col0 + arow) * Kd;

    uint32_t sbase = smem_u32(smem);
    uint32_t foff = (uint32_t)arow * ROWB + half * 32;

    float acc[4][4][4];
#pragma unroll
    for (int mt = 0; mt < 4; mt++)
#pragma unroll
        for (int nt = 0; nt < 4; nt++)
#pragma unroll
            for (int q = 0; q < 4; q++) acc[mt][nt][q] = 0.f;

    constexpr int KC = Kd / 32;

    auto fill = [&](int kc) {
        uint32_t dst = sbase + (uint32_t)(kc & (NSTG - 1)) * STAGE + foff;
        int k0 = kc * 32;
        const __half* s;
        s = Ar + k0 + half * 16;
        CP16Z(dst, s, asz); CP16Z(dst + 16, s + 8, asz);
        s = Br + k0 + half * 16;
        CP16(dst + REGION, s); CP16(dst + REGION + 16, s + 8);
    };

    fill(0); CP_COMMIT();
    fill(1); CP_COMMIT();
    fill(2); CP_COMMIT();

    uint32_t lrow = lid & 15;
    uint32_t lhalf = (lid >> 4) * 16;

    for (int kc = 0; kc < KC; kc++) {
        CP_WAIT2();
        __syncthreads();
        if (kc + 3 < KC) fill(kc + 3);
        CP_COMMIT();

        uint32_t st = sbase + (uint32_t)(kc & (NSTG - 1)) * STAGE;
#pragma unroll
        for (int ks = 0; ks < 2; ks++) {
            uint32_t koff = (uint32_t)ks * 32 + lhalf;
            uint32_t ah[4][4], bh[2][4];
#pragma unroll
            for (int mt = 0; mt < 4; mt++)
                ldm_x4(ah[mt], st + (uint32_t)(m_base + mt * 16 + lrow) * ROWB + koff);
#pragma unroll
            for (int p = 0; p < 2; p++)
                ldm_x4(bh[p], st + REGION + (uint32_t)(n_base + p * 16 + lrow) * ROWB + koff);
#pragma unroll
            for (int mt = 0; mt < 4; mt++)
#pragma unroll
                for (int p = 0; p < 2; p++) {
                    mma16816(acc[mt][2 * p],     ah[mt], bh[p][0], bh[p][2]);
                    mma16816(acc[mt][2 * p + 1], ah[mt], bh[p][1], bh[p][3]);
                }
        }
    }

    // ---- epilogue ----
    __half* Oh = nullptr;
    if (LAYER == 1)      Oh = g_a1;
    else if (LAYER == 2) Oh = g_a2;

#pragma unroll
    for (int mt = 0; mt < 4; mt++) {
        int rA = row0 + m_base + mt * 16 + g;
#pragma unroll
        for (int nt = 0; nt < 4; nt++) {
            int col = col0 + n_base + nt * 8 + t * 2;
            float2 bv = *(const float2*)(bias + col);
            float2 o0, o1;
            o0.x = acc[mt][nt][0] + bv.x; o0.y = acc[mt][nt][1] + bv.y;
            o1.x = acc[mt][nt][2] + bv.x; o1.y = acc[mt][nt][3] + bv.y;
            if (LAYER < 3) {
                o0.x = fmaxf(o0.x, 0.f); o0.y = fmaxf(o0.y, 0.f);
                o1.x = fmaxf(o1.x, 0.f); o1.y = fmaxf(o1.y, 0.f);
                __half2 h0 = __floats2half2_rn(o0.x, o0.y);
                __half2 h1 = __floats2half2_rn(o1.x, o1.y);
                *(uint32_t*)(Oh + (size_t)rA * Nd + col)       = *(uint32_t*)&h0;
                *(uint32_t*)(Oh + (size_t)(rA + 8) * Nd + col) = *(uint32_t*)&h1;
            } else {
                *(float2*)(g_or + (size_t)rA * Nd + col)       = o0;
                *(float2*)(g_or + (size_t)(rA + 8) * Nd + col) = o1;
            }
        }
    }
}

// ---------------- combine ----------------
__global__ void combine_k(float* __restrict__ out) {
    int t = blockIdx.x, c = threadIdx.x;
    int r0 = g_inv[t * 2], r1 = g_inv[t * 2 + 1];
    float w0 = g_gw[t * 2], w1 = g_gw[t * 2 + 1];
    const float4* a = (const float4*)(g_or + (size_t)r0 * DO_);
    const float4* b = (const float4*)(g_or + (size_t)r1 * DO_);
    float4 va = a[c], vb = b[c], o;
    o.x = w0 * va.x + w1 * vb.x;
    o.y = w0 * va.y + w1 * vb.y;
    o.z = w0 * va.z + w1 * vb.z;
    o.w = w0 * va.w + w1 * vb.w;
    ((float4*)(out + (size_t)t * DO_))[c] = o;
}

__global__ void idxout_k(float* __restrict__ dst, int n) {
    int i = blockIdx.x * blockDim.x + threadIdx.x;
    if (i < n) dst[i] = (float)g_idx[i];
}

// ---------------- launch: multi-stream fork/join (graph-capture compatible) ----
extern "C" void kernel_launch(void* const* d_in, const int* in_sizes, int n_in,
                              void* d_out, int out_size) {
    (void)in_sizes; (void)n_in;
    const float* xr = (const float*)d_in[0];
    const float* xe = (const float*)d_in[1];
    const float* Wg = (const float*)d_in[2];
    const float* bg = (const float*)d_in[3];
    const float* eb = (const float*)d_in[4];
    const float* W1 = (const float*)d_in[5];
    const float* b1 = (const float*)d_in[6];
    const float* W2 = (const float*)d_in[7];
    const float* b2 = (const float*)d_in[8];
    const float* W3 = (const float*)d_in[9];
    const float* b3 = (const float*)d_in[10];
    float* out = (float*)d_out;

    // lazily created host-side plumbing (streams/events; no device memory)
    static cudaStream_t sB = 0, sC = 0;
    static cudaEvent_t evRoot = 0, ev_w1 = 0, ev_w2 = 0, ev_w3 = 0;
    if (sB == 0) {
        cudaStreamCreateWithFlags(&sB, cudaStreamNonBlocking);
        cudaStreamCreateWithFlags(&sC, cudaStreamNonBlocking);
        cudaEventCreateWithFlags(&evRoot, cudaEventDisableTiming);
        cudaEventCreateWithFlags(&ev_w1, cudaEventDisableTiming);
        cudaEventCreateWithFlags(&ev_w2, cudaEventDisableTiming);
        cudaEventCreateWithFlags(&ev_w3, cudaEventDisableTiming);
    }

    cudaFuncSetAttribute(mma_gemm_k<1, DI_, H1_>, cudaFuncAttributeMaxDynamicSharedMemorySize, SMEM_GEMM);
    cudaFuncSetAttribute(mma_gemm_k<2, H1_, H2_>, cudaFuncAttributeMaxDynamicSharedMemorySize, SMEM_GEMM);
    cudaFuncSetAttribute(mma_gemm_k<3, H2_, DO_>, cudaFuncAttributeMaxDynamicSharedMemorySize, SMEM_GEMM);

    dim3 wt(32, 8);

    // ---- fork: sB (wsplit1) and sC (wsplit2,3) branch off the origin stream ----
    cudaEventRecord(evRoot, 0);
    cudaStreamWaitEvent(sB, evRoot, 0);

    // sB: weights for layer 1 (GEMM1 dependency)
    wsplit_k<1><<<dim3(H1_ / 32, DI_ / 32, E_), wt, 0, sB>>>(W1, DI_, H1_);
    cudaEventRecord(ev_w1, sB);

    // sC: weights for layers 2+3, start after wsplit1 so it doesn't steal its DRAM;
    // they then overlap with GEMM1 (MMA-bound) on the origin stream.
    cudaStreamWaitEvent(sC, ev_w1, 0);
    wsplit_k<2><<<dim3(H2_ / 32, H1_ / 32, E_), wt, 0, sC>>>(W2, H1_, H2_);
    cudaEventRecord(ev_w2, sC);
    wsplit_k<3><<<dim3(DO_ / 32, H2_ / 32, E_), wt, 0, sC>>>(W3, H2_, DO_);
    cudaEventRecord(ev_w3, sC);

    // origin stream: routing chain (runs concurrently with wsplit1)
    init_k<<<(MAXROWS_ + 255) / 256, 256>>>();
    router_k<<<B_, 256>>>(xr, Wg, bg, eb);
    xsplit_k<<<(B_ * DI_ / 4) / 256, 256>>>(xe);
    prefix_k<<<1, 1>>>();
    scatter_k<<<NS_ / 256, 256>>>();

    // ---- join + GEMM chain ----
    cudaStreamWaitEvent(0, ev_w1, 0);
    mma_gemm_k<1, DI_, H1_><<<dim3(H1_ / 128, MAXTILES_), 256, SMEM_GEMM>>>(b1);
    cudaStreamWaitEvent(0, ev_w2, 0);
    mma_gemm_k<2, H1_, H2_><<<dim3(H2_ / 128, MAXTILES_), 256, SMEM_GEMM>>>(b2);
    cudaStreamWaitEvent(0, ev_w3, 0);
    mma_gemm_k<3, H2_, DO_><<<dim3(DO_ / 128, MAXTILES_), 256, SMEM_GEMM>>>(b3);

    combine_k<<<B_, 256>>>(out);

    int tail = out_size - B_ * DO_;
    if (tail > 0) {
        int n = tail < NS_ ? tail : NS_;
        idxout_k<<<(n + 255) / 256, 256>>>(out + (size_t)B_ * DO_, n);
    }
}